// round 11
// baseline (speedup 1.0000x reference)
#include <cuda_runtime.h>
#include <cuda_fp16.h>
#include <cuda_bf16.h>
#include <stdint.h>
#include <cstdint>
#include <math.h>
#include <float.h>

typedef unsigned int u32;
typedef signed char s8;

#define S_   1024
#define D_   1024
#define H_   16
#define KV_  4
#define HD_  64
#define KVD_ 256
#define FF_  4096
#define L_   8
#define V_   50257
#define VPAD_ 50304
#define QKVD_ 1536
#define EPS_ 1.1920928955078125e-07f
#define QMAXI 32639
#define QMAXF 32639.0f

// ---------------- device globals ----------------
// int8 weights (exact q values) + per-row scale
__device__ s8 g_qw8  [L_ * QKVD_ * D_];
__device__ s8 g_qwo8 [L_ * D_   * D_ ];
__device__ s8 g_qwfc8[L_ * FF_  * D_ ];
__device__ s8 g_qwpr8[L_ * D_   * FF_];
__device__ s8 g_qlm8 [(size_t)VPAD_ * D_];
__device__ float g_sqkv[L_ * QKVD_];
__device__ float g_swo [L_ * D_ ];
__device__ float g_swfc[L_ * FF_];
__device__ float g_swpr[L_ * D_ ];
__device__ float g_slm [VPAD_];

__device__ float g_x  [S_ * D_ ];
__device__ float g_qkv[S_ * QKVD_];
__device__ float g_att[S_ * D_ ];
__device__ float g_ff [S_ * FF_];

// int16-split activations: hi/lo int8 planes + per-row scale
__device__ s8   g_h8h [S_ * D_ ];
__device__ s8   g_h8l [S_ * D_ ];
__device__ float g_hsc [S_];
__device__ s8   g_a8h [S_ * D_ ];
__device__ s8   g_a8l [S_ * D_ ];
__device__ float g_asc [S_];
__device__ s8   g_f8h [S_ * FF_];
__device__ s8   g_f8l [S_ * FF_];
__device__ float g_fsc [S_];

// flash attention operands (bf16 hi/lo)
__device__ __nv_bfloat16 g_qhi [S_ * D_ ];
__device__ __nv_bfloat16 g_qlo [S_ * D_ ];
__device__ __nv_bfloat16 g_khi [S_ * KVD_];
__device__ __nv_bfloat16 g_klo [S_ * KVD_];
__device__ __nv_bfloat16 g_vthi[KVD_ * S_];
__device__ __nv_bfloat16 g_vtlo[KVD_ * S_];

// ---------------- helpers ----------------
__device__ __forceinline__ u32 smem_u32(const void* p) {
    return (u32)__cvta_generic_to_shared(p);
}
__device__ __forceinline__ void cpasync16(u32 dst, const void* src) {
    asm volatile("cp.async.cg.shared.global [%0], [%1], 16;" :: "r"(dst), "l"(src));
}
__device__ __forceinline__ void ldm_x4(u32& r0, u32& r1, u32& r2, u32& r3, u32 a) {
    asm volatile("ldmatrix.sync.aligned.m8n8.x4.shared.b16 {%0,%1,%2,%3}, [%4];"
        : "=r"(r0), "=r"(r1), "=r"(r2), "=r"(r3) : "r"(a));
}
__device__ __forceinline__ void mma16816(float* d, const u32* a, const u32* b) {
    asm volatile("mma.sync.aligned.m16n8k16.row.col.f32.bf16.bf16.f32 "
        "{%0,%1,%2,%3}, {%4,%5,%6,%7}, {%8,%9}, {%0,%1,%2,%3};"
        : "+f"(d[0]), "+f"(d[1]), "+f"(d[2]), "+f"(d[3])
        : "r"(a[0]), "r"(a[1]), "r"(a[2]), "r"(a[3]), "r"(b[0]), "r"(b[1]));
}
__device__ __forceinline__ void mma8(int* d, const u32* a, const u32* b) {
    asm volatile("mma.sync.aligned.m16n8k32.row.col.s32.s8.s8.s32 "
        "{%0,%1,%2,%3}, {%4,%5,%6,%7}, {%8,%9}, {%0,%1,%2,%3};"
        : "+r"(d[0]), "+r"(d[1]), "+r"(d[2]), "+r"(d[3])
        : "r"(a[0]), "r"(a[1]), "r"(a[2]), "r"(a[3]), "r"(b[0]), "r"(b[1]));
}
__device__ __forceinline__ u32 sw128(u32 b) {
    return b ^ ((b >> 3) & 0x70u);
}
__device__ __forceinline__ void split_store(float v, __nv_bfloat16* hi, __nv_bfloat16* lo, size_t i) {
    __nv_bfloat16 h = __float2bfloat16(v);
    hi[i] = h;
    lo[i] = __float2bfloat16(v - __bfloat162float(h));
}
__device__ __forceinline__ void split2(float a, float b, u32& hi, u32& lo) {
    __nv_bfloat16 ha = __float2bfloat16(a), hb = __float2bfloat16(b);
    hi = (u32)__bfloat16_as_ushort(ha) | ((u32)__bfloat16_as_ushort(hb) << 16);
    lo = (u32)__bfloat16_as_ushort(__float2bfloat16(a - __bfloat162float(ha)))
       | ((u32)__bfloat16_as_ushort(__float2bfloat16(b - __bfloat162float(hb))) << 16);
}
// quantize to int16 split bytes
__device__ __forceinline__ void q16(float v, float inv, signed char& hb, signed char& lb) {
    int q = (int)rintf(v * inv);
    q = q < -QMAXI ? -QMAXI : (q > QMAXI ? QMAXI : q);
    signed char l = (signed char)(q & 0xFF);
    hb = (signed char)((q - (int)l) >> 8);
    lb = l;
}

template<int W> __device__ __forceinline__ s8* q8sel() {
    if (W == 0) return g_qw8;
    if (W == 1) return g_qwo8;
    if (W == 2) return g_qwfc8;
    if (W == 3) return g_qwpr8;
    return g_qlm8;
}
template<int W> __device__ __forceinline__ float* scsel() {
    if (W == 0) return g_sqkv;
    if (W == 1) return g_swo;
    if (W == 2) return g_swfc;
    if (W == 3) return g_swpr;
    return g_slm;
}
template<int A> __device__ __forceinline__ const s8* a8hsel() {
    if (A == 0) return g_h8h;
    if (A == 1) return g_a8h;
    return g_f8h;
}
template<int A> __device__ __forceinline__ const s8* a8lsel() {
    if (A == 0) return g_h8l;
    if (A == 1) return g_a8l;
    return g_f8l;
}
template<int A> __device__ __forceinline__ const float* ascsel() {
    if (A == 0) return g_hsc;
    if (A == 1) return g_asc;
    return g_fsc;
}

// ---------------- fake-quant: top-2 abs -> clip -> int8 q + scale ----------------
template<int WSEL, int NR4>
__global__ void quant_kernel(const float* __restrict__ W, int rpl, int ld, int off)
{
    const int n = NR4 * 1024;
    int blk = blockIdx.x;
    int l = blk / rpl, r = blk % rpl;
    int out_row = l * ld + off + r;
    const float4* w4 = (const float4*)(W + (size_t)blk * n);
    s8* qb = q8sel<WSEL>() + (size_t)out_row * n;
    int tid = threadIdx.x;

    float4 v[NR4];
    float m1 = 0.f, m2 = 0.f;
    #pragma unroll
    for (int j = 0; j < NR4; j++) {
        v[j] = w4[tid + j * 256];
        float a;
        a = fabsf(v[j].x); if (a > m1) { m2 = m1; m1 = a; } else if (a > m2) m2 = a;
        a = fabsf(v[j].y); if (a > m1) { m2 = m1; m1 = a; } else if (a > m2) m2 = a;
        a = fabsf(v[j].z); if (a > m1) { m2 = m1; m1 = a; } else if (a > m2) m2 = a;
        a = fabsf(v[j].w); if (a > m1) { m2 = m1; m1 = a; } else if (a > m2) m2 = a;
    }
    __shared__ float s1[256], s2[256];
    s1[tid] = m1; s2[tid] = m2;
    __syncthreads();
    for (int o = 128; o; o >>= 1) {
        if (tid < o) {
            float a1 = s1[tid], a2 = s2[tid];
            float b1 = s1[tid + o], b2 = s2[tid + o];
            s1[tid] = fmaxf(a1, b1);
            s2[tid] = fmaxf(fminf(a1, b1), fmaxf(a2, b2));
        }
        __syncthreads();
    }
    __shared__ float sh_clip, sh_scale;
    if (tid == 0) {
        float M1 = s1[0], M2 = s2[0];
        float idxf = 0.9999984f * (float)(n - 1);
        float frac = idxf - (float)(n - 2);
        float clip = M2 * (1.0f - frac) + M1 * frac;
        float scale = fmaxf(__fdiv_rn(clip, 127.0f), 1.0f / 127.0f);
        sh_clip = clip;
        sh_scale = scale;
        scsel<WSEL>()[out_row] = __half2float(__float2half_rn(scale));
    }
    __syncthreads();
    float clip = sh_clip, scale = sh_scale;
    #pragma unroll
    for (int j = 0; j < NR4; j++) {
        float q[4];
        float* vv = (float*)&v[j];
        #pragma unroll
        for (int e = 0; e < 4; e++) {
            float c = fminf(fmaxf(vv[e], -clip), clip);
            float t = rintf(__fdiv_rn(c, scale));
            q[e] = fminf(fmaxf(t, -127.f), 127.f);
        }
        char4 out;
        out.x = (s8)(int)q[0]; out.y = (s8)(int)q[1];
        out.z = (s8)(int)q[2]; out.w = (s8)(int)q[3];
        ((char4*)qb)[tid + j * 256] = out;
    }
}

// ---------------- embedding ----------------
__global__ void embed_kernel(const int* __restrict__ idx, const float* __restrict__ emb)
{
    int i = blockIdx.x * blockDim.x + threadIdx.x;
    int s = i >> 10, d = i & 1023;
    g_x[i] = emb[(size_t)idx[s] * D_ + d];
}

// ---------------- rmsnorm -> int16-split int8 + row scale ----------------
__global__ void rmsnorm8_kernel()
{
    int row = blockIdx.x, tid = threadIdx.x;
    float4 v = ((const float4*)(g_x + (size_t)row * D_))[tid];
    float ss = v.x * v.x + v.y * v.y + v.z * v.z + v.w * v.w;
    float am = fmaxf(fmaxf(fabsf(v.x), fabsf(v.y)), fmaxf(fabsf(v.z), fabsf(v.w)));
    __shared__ float sh[256], sm[256];
    sh[tid] = ss; sm[tid] = am;
    __syncthreads();
    for (int o = 128; o; o >>= 1) {
        if (tid < o) { sh[tid] += sh[tid + o]; sm[tid] = fmaxf(sm[tid], sm[tid + o]); }
        __syncthreads();
    }
    float r = rsqrtf(sh[0] / (float)D_ + EPS_);
    float s = fmaxf(sm[0] * r, 1e-20f) * (1.0f / QMAXF);
    float inv = 1.0f / s;
    if (tid == 0) g_hsc[row] = s;
    char4 hb, lb;
    q16(v.x * r, inv, hb.x, lb.x);
    q16(v.y * r, inv, hb.y, lb.y);
    q16(v.z * r, inv, hb.z, lb.z);
    q16(v.w * r, inv, hb.w, lb.w);
    ((char4*)(g_h8h + (size_t)row * D_))[tid] = hb;
    ((char4*)(g_h8l + (size_t)row * D_))[tid] = lb;
}

// ---------------- fp32 -> int16-split repack (att, ff) ----------------
template<int ABUF, int NR4>
__global__ void repack8_kernel()
{
    const int n = NR4 * 1024;
    int row = blockIdx.x, tid = threadIdx.x;
    const float* in = (ABUF == 1) ? g_att : g_ff;
    s8* hp = (ABUF == 1) ? g_a8h : g_f8h;
    s8* lp = (ABUF == 1) ? g_a8l : g_f8l;
    float* sc = (ABUF == 1) ? g_asc : g_fsc;

    const float4* xr = (const float4*)(in + (size_t)row * n);
    float4 v[NR4];
    float am = 0.f;
    #pragma unroll
    for (int j = 0; j < NR4; j++) {
        v[j] = xr[tid + j * 256];
        am = fmaxf(am, fmaxf(fmaxf(fabsf(v[j].x), fabsf(v[j].y)),
                             fmaxf(fabsf(v[j].z), fabsf(v[j].w))));
    }
    __shared__ float sm[256];
    sm[tid] = am;
    __syncthreads();
    for (int o = 128; o; o >>= 1) {
        if (tid < o) sm[tid] = fmaxf(sm[tid], sm[tid + o]);
        __syncthreads();
    }
    float s = fmaxf(sm[0], 1e-20f) * (1.0f / QMAXF);
    float inv = 1.0f / s;
    if (tid == 0) sc[row] = s;
    #pragma unroll
    for (int j = 0; j < NR4; j++) {
        char4 hb, lb;
        q16(v[j].x, inv, hb.x, lb.x);
        q16(v[j].y, inv, hb.y, lb.y);
        q16(v[j].z, inv, hb.z, lb.z);
        q16(v[j].w, inv, hb.w, lb.w);
        ((char4*)(hp + (size_t)row * n))[tid + j * 256] = hb;
        ((char4*)(lp + (size_t)row * n))[tid + j * 256] = lb;
    }
}

// ---------------- per-head RMS + RoPE + gain (q pre-scaled by 1/8) ----------------
__global__ void qkpost_kernel(const float* __restrict__ gain, int nh, int off, int isq)
{
    int warp = (blockIdx.x * blockDim.x + threadIdx.x) >> 5;
    int lane = threadIdx.x & 31;
    int s = warp / nh, h = warp % nh;
    if (s >= S_) return;
    const float* base = g_qkv + (size_t)s * QKVD_ + off + h * HD_;
    float e0 = base[lane], e1 = base[lane + 32];
    float ss = e0 * e0 + e1 * e1;
    #pragma unroll
    for (int o = 16; o; o >>= 1) ss += __shfl_xor_sync(0xffffffffu, ss, o);
    float r = rsqrtf(ss * (1.f / 64.f) + EPS_);
    e0 *= r; e1 *= r;
    float inv = (float)exp(-((double)lane / 32.0) * 9.210340371976184);
    float f = (float)s * inv;
    float c  = (float)cos((double)f);
    float sn = (float)sin((double)f);
    float o0 =  e0 * c + e1 * sn;
    float o1 = -e0 * sn + e1 * c;
    if (isq) {
        float g = gain[h] * 0.125f;
        split_store(o0 * g, g_qhi, g_qlo, (size_t)s * D_ + h * HD_ + lane);
        split_store(o1 * g, g_qhi, g_qlo, (size_t)s * D_ + h * HD_ + lane + 32);
    } else {
        split_store(o0, g_khi, g_klo, (size_t)s * KVD_ + h * HD_ + lane);
        split_store(o1, g_khi, g_klo, (size_t)s * KVD_ + h * HD_ + lane + 32);
    }
}

// ---------------- V transpose ----------------
__global__ void vtrans_kernel()
{
    __shared__ float t[32][33];
    int s0 = blockIdx.x * 32, c0 = blockIdx.y * 32;
    int tx = threadIdx.x, ty = threadIdx.y;
    #pragma unroll
    for (int k = 0; k < 32; k += 8)
        t[ty + k][tx] = g_qkv[(size_t)(s0 + ty + k) * QKVD_ + 1280 + c0 + tx];
    __syncthreads();
    #pragma unroll
    for (int k = 0; k < 32; k += 8) {
        float v = t[tx][ty + k];
        split_store(v, g_vthi, g_vtlo, (size_t)(c0 + ty + k) * S_ + s0 + tx);
    }
}

// ---------------- fused flash attention (fp32 output) ----------------
#define FA_DSM (16384 + 2 * 32768 + 1024)

__global__ __launch_bounds__(128, 1) void flash_kernel()
{
    int bi = 15 - (int)blockIdx.x;
    int h = blockIdx.y, kvh = h >> 2;
    extern __shared__ char fsm[];
    u32 base = (smem_u32(fsm) + 1023u) & ~1023u;

    int tid = threadIdx.x, lane = tid & 31, w = tid >> 5;
    int tig = lane & 3, grp = lane >> 2;

    for (int id = tid; id < 512; id += 128) {
        int r = id >> 3, ck = id & 7;
        u32 so = sw128((u32)(r * 128 + ck * 16));
        size_t gq = (size_t)(bi * 64 + r) * D_ + h * HD_ + ck * 8;
        cpasync16(base + so, g_qhi + gq);
        cpasync16(base + 8192 + so, g_qlo + gq);
    }
    asm volatile("cp.async.commit_group;");

    #define FA_LOAD(st, jt) do { \
        u32 sb_ = base + 16384 + (u32)(st) * 32768; \
        for (int id_ = tid; id_ < 512; id_ += 128) { \
            int r_ = id_ >> 3, ck_ = id_ & 7; \
            u32 so_ = sw128((u32)(r_ * 128 + ck_ * 16)); \
            size_t gk_ = (size_t)((jt) * 64 + r_) * KVD_ + kvh * HD_ + ck_ * 8; \
            cpasync16(sb_ + so_,         g_khi + gk_); \
            cpasync16(sb_ + 8192 + so_,  g_klo + gk_); \
            size_t gv_ = (size_t)(kvh * 64 + r_) * S_ + (jt) * 64 + ck_ * 8; \
            cpasync16(sb_ + 16384 + so_, g_vthi + gv_); \
            cpasync16(sb_ + 24576 + so_, g_vtlo + gv_); \
        } \
        asm volatile("cp.async.commit_group;"); \
    } while (0)

    int n = bi + 1;
    FA_LOAD(0, 0);

    asm volatile("cp.async.wait_group 1;");
    __syncthreads();
    u32 qh[4][4], ql[4][4];
    #pragma unroll
    for (int kc = 0; kc < 4; kc++) {
        int lr = w * 16 + (lane & 15);
        int ch = kc * 2 + (lane >> 4);
        u32 so = sw128((u32)(lr * 128 + ch * 16));
        ldm_x4(qh[kc][0], qh[kc][1], qh[kc][2], qh[kc][3], base + so);
        ldm_x4(ql[kc][0], ql[kc][1], ql[kc][2], ql[kc][3], base + 8192 + so);
    }

    float o[8][4];
    #pragma unroll
    for (int nd = 0; nd < 8; nd++) { o[nd][0]=0.f; o[nd][1]=0.f; o[nd][2]=0.f; o[nd][3]=0.f; }
    float m0 = -1e30f, m1 = -1e30f, l0 = 0.f, l1 = 0.f;

    for (int jt = 0; jt < n; jt++) {
        if (jt + 1 < n) {
            FA_LOAD((jt + 1) & 1, jt + 1);
            asm volatile("cp.async.wait_group 1;");
        } else {
            asm volatile("cp.async.wait_group 0;");
        }
        __syncthreads();

        u32 kb = base + 16384 + (u32)(jt & 1) * 32768;

        float s[8][4];
        #pragma unroll
        for (int ni = 0; ni < 8; ni++) { s[ni][0]=0.f; s[ni][1]=0.f; s[ni][2]=0.f; s[ni][3]=0.f; }
        #pragma unroll
        for (int kc = 0; kc < 4; kc++) {
            u32 bh[8][2], bl[8][2];
            #pragma unroll
            for (int nj = 0; nj < 4; nj++) {
                int g = lane >> 3;
                int lr = nj * 16 + (((g >> 1) & 1) << 3) + (lane & 7);
                int ch = kc * 2 + (g & 1);
                u32 so = sw128((u32)(lr * 128 + ch * 16));
                u32 r0, r1, r2, r3;
                ldm_x4(r0, r1, r2, r3, kb + so);
                bh[nj * 2][0] = r0; bh[nj * 2][1] = r1;
                bh[nj * 2 + 1][0] = r2; bh[nj * 2 + 1][1] = r3;
                ldm_x4(r0, r1, r2, r3, kb + 8192 + so);
                bl[nj * 2][0] = r0; bl[nj * 2][1] = r1;
                bl[nj * 2 + 1][0] = r2; bl[nj * 2 + 1][1] = r3;
            }
            #pragma unroll
            for (int ni = 0; ni < 8; ni++) {
                mma16816(s[ni], qh[kc], bh[ni]);
                mma16816(s[ni], qh[kc], bl[ni]);
                mma16816(s[ni], ql[kc], bh[ni]);
            }
        }

        if (jt == bi) {
            int ci0 = w * 16 + grp, ci1 = ci0 + 8;
            #pragma unroll
            for (int ni = 0; ni < 8; ni++) {
                int cj = ni * 8 + tig * 2;
                if (cj     > ci0) s[ni][0] = -1e30f;
                if (cj + 1 > ci0) s[ni][1] = -1e30f;
                if (cj     > ci1) s[ni][2] = -1e30f;
                if (cj + 1 > ci1) s[ni][3] = -1e30f;
            }
        }

        float tm0 = -1e30f, tm1 = -1e30f;
        #pragma unroll
        for (int ni = 0; ni < 8; ni++) {
            tm0 = fmaxf(tm0, fmaxf(s[ni][0], s[ni][1]));
            tm1 = fmaxf(tm1, fmaxf(s[ni][2], s[ni][3]));
        }
        tm0 = fmaxf(tm0, __shfl_xor_sync(0xffffffffu, tm0, 1));
        tm0 = fmaxf(tm0, __shfl_xor_sync(0xffffffffu, tm0, 2));
        tm1 = fmaxf(tm1, __shfl_xor_sync(0xffffffffu, tm1, 1));
        tm1 = fmaxf(tm1, __shfl_xor_sync(0xffffffffu, tm1, 2));
        float mn0 = fmaxf(m0, tm0), mn1 = fmaxf(m1, tm1);
        float a0 = expf(m0 - mn0), a1 = expf(m1 - mn1);
        m0 = mn0; m1 = mn1;

        float rs0 = 0.f, rs1 = 0.f;
        #pragma unroll
        for (int ni = 0; ni < 8; ni++) {
            s[ni][0] = expf(s[ni][0] - mn0);
            s[ni][1] = expf(s[ni][1] - mn0);
            s[ni][2] = expf(s[ni][2] - mn1);
            s[ni][3] = expf(s[ni][3] - mn1);
            rs0 += s[ni][0] + s[ni][1];
            rs1 += s[ni][2] + s[ni][3];
        }
        rs0 += __shfl_xor_sync(0xffffffffu, rs0, 1);
        rs0 += __shfl_xor_sync(0xffffffffu, rs0, 2);
        rs1 += __shfl_xor_sync(0xffffffffu, rs1, 1);
        rs1 += __shfl_xor_sync(0xffffffffu, rs1, 2);
        l0 = l0 * a0 + rs0;
        l1 = l1 * a1 + rs1;
        #pragma unroll
        for (int nd = 0; nd < 8; nd++) {
            o[nd][0] *= a0; o[nd][1] *= a0;
            o[nd][2] *= a1; o[nd][3] *= a1;
        }

        u32 vbh = kb + 16384, vbl = kb + 24576;
        #pragma unroll
        for (int kc = 0; kc < 4; kc++) {
            u32 pah[4], pal[4];
            split2(s[2 * kc][0],     s[2 * kc][1],     pah[0], pal[0]);
            split2(s[2 * kc][2],     s[2 * kc][3],     pah[1], pal[1]);
            split2(s[2 * kc + 1][0], s[2 * kc + 1][1], pah[2], pal[2]);
            split2(s[2 * kc + 1][2], s[2 * kc + 1][3], pah[3], pal[3]);
            u32 vh[8][2], vl[8][2];
            #pragma unroll
            for (int nj = 0; nj < 4; nj++) {
                int g = lane >> 3;
                int lr = nj * 16 + (((g >> 1) & 1) << 3) + (lane & 7);
                int ch = kc * 2 + (g & 1);
                u32 so = sw128((u32)(lr * 128 + ch * 16));
                u32 r0, r1, r2, r3;
                ldm_x4(r0, r1, r2, r3, vbh + so);
                vh[nj * 2][0] = r0; vh[nj * 2][1] = r1;
                vh[nj * 2 + 1][0] = r2; vh[nj * 2 + 1][1] = r3;
                ldm_x4(r0, r1, r2, r3, vbl + so);
                vl[nj * 2][0] = r0; vl[nj * 2][1] = r1;
                vl[nj * 2 + 1][0] = r2; vl[nj * 2 + 1][1] = r3;
            }
            #pragma unroll
            for (int nd = 0; nd < 8; nd++) {
                mma16816(o[nd], pah, vh[nd]);
                mma16816(o[nd], pah, vl[nd]);
                mma16816(o[nd], pal, vh[nd]);
            }
        }
        __syncthreads();
    }

    float inv0 = 1.0f / l0, inv1 = 1.0f / l1;
    int gi0 = bi * 64 + w * 16 + grp;
    #pragma unroll
    for (int nd = 0; nd < 8; nd++) {
        int gd = h * HD_ + nd * 8 + tig * 2;
        g_att[(size_t)gi0 * D_ + gd]           = o[nd][0] * inv0;
        g_att[(size_t)gi0 * D_ + gd + 1]       = o[nd][1] * inv0;
        g_att[(size_t)(gi0 + 8) * D_ + gd]     = o[nd][2] * inv1;
        g_att[(size_t)(gi0 + 8) * D_ + gd + 1] = o[nd][3] * inv1;
    }
    #undef FA_LOAD
}

// ---------------- INT8 weight GEMM: stage K=128, 3-stage pipeline ----------------
template<int BM, int BN>
__device__ __forceinline__ void load_stage8(
    const s8* Ahi, const s8* Alo, const s8* Bq,
    u32 sbase, int row0, int col0, int K, int k0, int tid)
{
    constexpr u32 AB = (u32)BM * 128;
    for (int id = tid; id < BM * 8; id += 256) {
        int r = id >> 3, ck = id & 7;
        u32 so = sw128((u32)(r * 128 + ck * 16));
        size_t g = (size_t)(row0 + r) * K + k0 + ck * 16;
        cpasync16(sbase + so, Ahi + g);
        cpasync16(sbase + AB + so, Alo + g);
    }
    for (int id = tid; id < BN * 8; id += 256) {
        int r = id >> 3, ck = id & 7;
        u32 so = sw128((u32)(r * 128 + ck * 16));
        cpasync16(sbase + 2 * AB + so, Bq + (size_t)(col0 + r) * K + k0 + ck * 16);
    }
    asm volatile("cp.async.commit_group;");
}

// EPI: 0 = write g_qkv, 1 = residual add into g_x, 2 = relu^2 fp32 to g_ff, 3 = write Cout
template<int BM, int BN, int WM, int WN, int EPI, int WSEL, int ASEL>
__global__ __launch_bounds__(256, 1)
void qgemm8_kernel(float* __restrict__ Cout, int layer, int N, int K, int ldc)
{
    constexpr int TM = BM / WM, TN = BN / WN;
    constexpr int MI = TM / 16, NI = TN / 8;
    constexpr u32 STB = (u32)(2 * BM + BN) * 128;

    extern __shared__ char dsm[];
    u32 base = (smem_u32(dsm) + 1023u) & ~1023u;

    int tid = threadIdx.x, lane = tid & 31, wid = tid >> 5;
    int wm = wid % WM, wn = wid / WM;
    int row0 = blockIdx.y * BM, col0 = blockIdx.x * BN;

    const s8* Ahi = a8hsel<ASEL>();
    const s8* Alo = a8lsel<ASEL>();
    const s8* Bq  = q8sel<WSEL>() + (size_t)layer * N * K;
    const float* Sc = scsel<WSEL>() + (size_t)layer * N;
    const float* Asc = ascsel<ASEL>();

    int acch[MI][NI][4], accl[MI][NI][4];
    #pragma unroll
    for (int mi = 0; mi < MI; mi++) {
        #pragma unroll
        for (int ni = 0; ni < NI; ni++) {
            #pragma unroll
            for (int e = 0; e < 4; e++) { acch[mi][ni][e] = 0; accl[mi][ni][e] = 0; }
        }
    }

    int n = K >> 7;
    load_stage8<BM, BN>(Ahi, Alo, Bq, base,       row0, col0, K, 0,   tid);
    load_stage8<BM, BN>(Ahi, Alo, Bq, base + STB, row0, col0, K, 128, tid);

    for (int it = 0; it < n; it++) {
        asm volatile("cp.async.wait_group 1;");
        __syncthreads();

        int ldst = it + 2;
        if (ldst < n) {
            load_stage8<BM, BN>(Ahi, Alo, Bq, base + (u32)(ldst % 3) * STB,
                                row0, col0, K, ldst << 7, tid);
        } else {
            asm volatile("cp.async.commit_group;");
        }

        u32 sb = base + (u32)(it % 3) * STB;
        #pragma unroll
        for (int kc = 0; kc < 4; kc++) {
            u32 ah[MI][4], al[MI][4];
            #pragma unroll
            for (int mi = 0; mi < MI; mi++) {
                int lr = wm * TM + mi * 16 + (lane & 15);
                int ch = kc * 2 + (lane >> 4);
                u32 so = sw128((u32)(lr * 128 + ch * 16));
                ldm_x4(ah[mi][0], ah[mi][1], ah[mi][2], ah[mi][3], sb + so);
                ldm_x4(al[mi][0], al[mi][1], al[mi][2], al[mi][3], sb + (u32)BM * 128 + so);
            }
            u32 bb[NI][2];
            #pragma unroll
            for (int nj = 0; nj < NI / 2; nj++) {
                int g = lane >> 3;
                int lr = wn * TN + nj * 16 + (((g >> 1) & 1) << 3) + (lane & 7);
                int ch = kc * 2 + (g & 1);
                u32 r0, r1, r2, r3;
                ldm_x4(r0, r1, r2, r3, sb + 2u * BM * 128 + sw128((u32)(lr * 128 + ch * 16)));
                bb[nj * 2][0] = r0; bb[nj * 2][1] = r1;
                bb[nj * 2 + 1][0] = r2; bb[nj * 2 + 1][1] = r3;
            }
            #pragma unroll
            for (int mi = 0; mi < MI; mi++) {
                #pragma unroll
                for (int ni = 0; ni < NI; ni++) {
                    mma8(acch[mi][ni], ah[mi], bb[ni]);
                    mma8(accl[mi][ni], al[mi], bb[ni]);
                }
            }
        }
    }

    #pragma unroll
    for (int mi = 0; mi < MI; mi++) {
        #pragma unroll
        for (int ni = 0; ni < NI; ni++) {
            int gr0 = row0 + wm * TM + mi * 16 + (lane >> 2);
            int gc  = col0 + wn * TN + ni * 8 + ((lane & 3) << 1);
            #pragma unroll
            for (int half = 0; half < 2; half++) {
                int gr = gr0 + half * 8;
                float as = Asc[gr];
                #pragma unroll
                for (int e = 0; e < 2; e++) {
                    int c = gc + e;
                    if (c >= N) continue;
                    float dot = 256.0f * (float)acch[mi][ni][half * 2 + e]
                              + (float)accl[mi][ni][half * 2 + e];
                    float v = dot * as * Sc[c];
                    if (EPI == 0) {
                        g_qkv[(size_t)gr * QKVD_ + c] = v;
                    } else if (EPI == 1) {
                        g_x[(size_t)gr * D_ + c] += v;
                    } else if (EPI == 2) {
                        float t = fmaxf(v, 0.f);
                        g_ff[(size_t)gr * FF_ + c] = t * t;
                    } else {
                        Cout[(size_t)gr * ldc + c] = v;
                    }
                }
            }
        }
    }
}

#define DSM_SMALL (3 * (2 * 128 + 64)  * 128 + 1024)
#define DSM_BIG   (3 * (2 * 128 + 128) * 128 + 1024)

// ---------------- host orchestration ----------------
extern "C" void kernel_launch(void* const* d_in, const int* in_sizes, int n_in,
                              void* d_out, int out_size)
{
    (void)in_sizes; (void)n_in; (void)out_size;
    const int*   idx = (const int*)  d_in[0];
    const float* emb = (const float*)d_in[1];
    const float* wq  = (const float*)d_in[2];
    const float* wk  = (const float*)d_in[3];
    const float* wv  = (const float*)d_in[4];
    const float* wo  = (const float*)d_in[5];
    const float* qg  = (const float*)d_in[6];
    const float* wfc = (const float*)d_in[7];
    const float* wpr = (const float*)d_in[8];
    const float* lm  = (const float*)d_in[9];
    float* out = (float*)d_out;

    cudaFuncSetAttribute(qgemm8_kernel<128, 64, 4, 2, 0, 0, 0>,
                         cudaFuncAttributeMaxDynamicSharedMemorySize, DSM_SMALL);
    cudaFuncSetAttribute(qgemm8_kernel<128, 64, 4, 2, 1, 1, 1>,
                         cudaFuncAttributeMaxDynamicSharedMemorySize, DSM_SMALL);
    cudaFuncSetAttribute(qgemm8_kernel<128, 128, 2, 4, 2, 2, 0>,
                         cudaFuncAttributeMaxDynamicSharedMemorySize, DSM_BIG);
    cudaFuncSetAttribute(qgemm8_kernel<128, 64, 4, 2, 1, 3, 2>,
                         cudaFuncAttributeMaxDynamicSharedMemorySize, DSM_SMALL);
    cudaFuncSetAttribute(qgemm8_kernel<128, 128, 2, 4, 3, 4, 0>,
                         cudaFuncAttributeMaxDynamicSharedMemorySize, DSM_BIG);
    cudaFuncSetAttribute(flash_kernel,
                         cudaFuncAttributeMaxDynamicSharedMemorySize, FA_DSM);

    quant_kernel<0, 1><<<L_ * D_,   256>>>(wq,  D_,   QKVD_, 0);
    quant_kernel<0, 1><<<L_ * KVD_, 256>>>(wk,  KVD_, QKVD_, 1024);
    quant_kernel<0, 1><<<L_ * KVD_, 256>>>(wv,  KVD_, QKVD_, 1280);
    quant_kernel<1, 1><<<L_ * D_,   256>>>(wo,  L_ * D_,  0, 0);
    quant_kernel<2, 1><<<L_ * FF_,  256>>>(wfc, L_ * FF_, 0, 0);
    quant_kernel<3, 4><<<L_ * D_,   256>>>(wpr, L_ * D_,  0, 0);
    quant_kernel<4, 1><<<V_,        256>>>(lm,  V_,       0, 0);

    embed_kernel<<<(S_ * D_) / 256, 256>>>(idx, emb);

    for (int l = 0; l < L_; l++) {
        rmsnorm8_kernel<<<S_, 256>>>();

        qgemm8_kernel<128, 64, 4, 2, 0, 0, 0><<<dim3(QKVD_ / 64, S_ / 128), 256, DSM_SMALL>>>(
            nullptr, l, QKVD_, D_, QKVD_);

        qkpost_kernel<<<(S_ * H_)  / 4, 128>>>(qg + l * H_, H_,  0,    1);
        qkpost_kernel<<<(S_ * KV_) / 4, 128>>>(nullptr,     KV_, 1024, 0);
        vtrans_kernel<<<dim3(S_ / 32, KVD_ / 32), dim3(32, 8)>>>();

        flash_kernel<<<dim3(16, H_), 128, FA_DSM>>>();
        repack8_kernel<1, 1><<<S_, 256>>>();

        qgemm8_kernel<128, 64, 4, 2, 1, 1, 1><<<dim3(D_ / 64, S_ / 128), 256, DSM_SMALL>>>(
            nullptr, l, D_, D_, D_);

        rmsnorm8_kernel<<<S_, 256>>>();

        qgemm8_kernel<128, 128, 2, 4, 2, 2, 0><<<dim3(FF_ / 128, S_ / 128), 256, DSM_BIG>>>(
            nullptr, l, FF_, D_, FF_);
        repack8_kernel<2, 4><<<S_, 256>>>();

        qgemm8_kernel<128, 64, 4, 2, 1, 3, 2><<<dim3(D_ / 64, S_ / 128), 256, DSM_SMALL>>>(
            nullptr, l, D_, FF_, D_);
    }

    rmsnorm8_kernel<<<S_, 256>>>();
    qgemm8_kernel<128, 128, 2, 4, 3, 4, 0><<<dim3(VPAD_ / 128, S_ / 128), 256, DSM_BIG>>>(
        out, 0, V_, D_, V_);
}

// round 12
// speedup vs baseline: 1.8327x; 1.8327x over previous
#include <cuda_runtime.h>
#include <cuda_fp16.h>
#include <cuda_bf16.h>
#include <stdint.h>
#include <cstdint>
#include <math.h>
#include <float.h>

typedef unsigned int u32;

#define S_   1024
#define D_   1024
#define H_   16
#define KV_  4
#define HD_  64
#define KVD_ 256
#define FF_  4096
#define L_   8
#define V_   50257
#define VPAD_ 50304
#define QKVD_ 1536
#define EPS_ 1.1920928955078125e-07f

// ---------------- device globals ----------------
__device__ __nv_bfloat16 g_qw  [L_ * QKVD_ * D_];
__device__ __nv_bfloat16 g_qwo [L_ * D_   * D_ ];
__device__ __nv_bfloat16 g_qwfc[L_ * FF_  * D_ ];
__device__ __nv_bfloat16 g_qwpr[L_ * D_   * FF_];
__device__ __nv_bfloat16 g_qlm [(size_t)VPAD_ * D_];
__device__ float g_sqkv[L_ * QKVD_];
__device__ float g_swo [L_ * D_ ];
__device__ float g_swfc[L_ * FF_];
__device__ float g_swpr[L_ * D_ ];
__device__ float g_slm [VPAD_];

__device__ float g_x  [S_ * D_ ];
__device__ __nv_bfloat16 g_hhi[S_ * D_ ];
__device__ __nv_bfloat16 g_hlo[S_ * D_ ];
__device__ float g_qkv[S_ * QKVD_];
__device__ __nv_bfloat16 g_atthi[S_ * D_];
__device__ __nv_bfloat16 g_attlo[S_ * D_];
__device__ __nv_bfloat16 g_ffhi [S_ * FF_];
__device__ __nv_bfloat16 g_fflo [S_ * FF_];

__device__ __nv_bfloat16 g_qhi [S_ * D_ ];
__device__ __nv_bfloat16 g_qlo [S_ * D_ ];
__device__ __nv_bfloat16 g_khi [S_ * KVD_];
__device__ __nv_bfloat16 g_klo [S_ * KVD_];
__device__ __nv_bfloat16 g_vthi[KVD_ * S_];
__device__ __nv_bfloat16 g_vtlo[KVD_ * S_];

// ---------------- helpers ----------------
__device__ __forceinline__ u32 smem_u32(const void* p) {
    return (u32)__cvta_generic_to_shared(p);
}
__device__ __forceinline__ void cpasync16(u32 dst, const void* src) {
    asm volatile("cp.async.cg.shared.global [%0], [%1], 16;" :: "r"(dst), "l"(src));
}
__device__ __forceinline__ void ldm_x4(u32& r0, u32& r1, u32& r2, u32& r3, u32 a) {
    asm volatile("ldmatrix.sync.aligned.m8n8.x4.shared.b16 {%0,%1,%2,%3}, [%4];"
        : "=r"(r0), "=r"(r1), "=r"(r2), "=r"(r3) : "r"(a));
}
__device__ __forceinline__ void mma16816(float* d, const u32* a, const u32* b) {
    asm volatile("mma.sync.aligned.m16n8k16.row.col.f32.bf16.bf16.f32 "
        "{%0,%1,%2,%3}, {%4,%5,%6,%7}, {%8,%9}, {%0,%1,%2,%3};"
        : "+f"(d[0]), "+f"(d[1]), "+f"(d[2]), "+f"(d[3])
        : "r"(a[0]), "r"(a[1]), "r"(a[2]), "r"(a[3]), "r"(b[0]), "r"(b[1]));
}
__device__ __forceinline__ u32 sw128(u32 b) {              // 128B rows
    return b ^ ((b >> 3) & 0x70u);
}
__device__ __forceinline__ void split_store(float v, __nv_bfloat16* hi, __nv_bfloat16* lo, size_t i) {
    __nv_bfloat16 h = __float2bfloat16(v);
    hi[i] = h;
    lo[i] = __float2bfloat16(v - __bfloat162float(h));
}
__device__ __forceinline__ void split2(float a, float b, u32& hi, u32& lo) {
    __nv_bfloat16 ha = __float2bfloat16(a), hb = __float2bfloat16(b);
    hi = (u32)__bfloat16_as_ushort(ha) | ((u32)__bfloat16_as_ushort(hb) << 16);
    lo = (u32)__bfloat16_as_ushort(__float2bfloat16(a - __bfloat162float(ha)))
       | ((u32)__bfloat16_as_ushort(__float2bfloat16(b - __bfloat162float(hb))) << 16);
}

template<int W> __device__ __forceinline__ __nv_bfloat16* qsel() {
    if (W == 0) return g_qw;
    if (W == 1) return g_qwo;
    if (W == 2) return g_qwfc;
    if (W == 3) return g_qwpr;
    return g_qlm;
}
template<int W> __device__ __forceinline__ float* scsel() {
    if (W == 0) return g_sqkv;
    if (W == 1) return g_swo;
    if (W == 2) return g_swfc;
    if (W == 3) return g_swpr;
    return g_slm;
}
template<int A> __device__ __forceinline__ const __nv_bfloat16* ahisel() {
    if (A == 0) return g_hhi;
    if (A == 1) return g_atthi;
    return g_ffhi;
}
template<int A> __device__ __forceinline__ const __nv_bfloat16* alosel() {
    if (A == 0) return g_hlo;
    if (A == 1) return g_attlo;
    return g_fflo;
}

// ---------------- fake-quant ----------------
template<int WSEL, int NR>
__global__ void quant_kernel(const float* __restrict__ W, int rpl, int ld, int off)
{
    const int n = NR * 256;
    int blk = blockIdx.x;
    int l = blk / rpl, r = blk % rpl;
    int out_row = l * ld + off + r;
    const float* w = W + (size_t)blk * n;
    __nv_bfloat16* qb = qsel<WSEL>() + (size_t)out_row * n;
    int tid = threadIdx.x;

    float v[NR];
    float m1 = 0.f, m2 = 0.f;
    #pragma unroll
    for (int j = 0; j < NR; j++) {
        v[j] = w[tid + j * 256];
        float a = fabsf(v[j]);
        if (a > m1) { m2 = m1; m1 = a; }
        else if (a > m2) { m2 = a; }
    }
    __shared__ float s1[256], s2[256];
    s1[tid] = m1; s2[tid] = m2;
    __syncthreads();
    for (int o = 128; o; o >>= 1) {
        if (tid < o) {
            float a1 = s1[tid], a2 = s2[tid];
            float b1 = s1[tid + o], b2 = s2[tid + o];
            s1[tid] = fmaxf(a1, b1);
            s2[tid] = fmaxf(fminf(a1, b1), fmaxf(a2, b2));
        }
        __syncthreads();
    }
    __shared__ float sh_clip, sh_scale;
    if (tid == 0) {
        float M1 = s1[0], M2 = s2[0];
        float idxf = 0.9999984f * (float)(n - 1);
        float frac = idxf - (float)(n - 2);
        float clip = M2 * (1.0f - frac) + M1 * frac;
        float scale = fmaxf(__fdiv_rn(clip, 127.0f), 1.0f / 127.0f);
        sh_clip = clip;
        sh_scale = scale;
        scsel<WSEL>()[out_row] = __half2float(__float2half_rn(scale));
    }
    __syncthreads();
    float clip = sh_clip, scale = sh_scale;
    #pragma unroll
    for (int j = 0; j < NR; j++) {
        float c = fminf(fmaxf(v[j], -clip), clip);
        float q = rintf(__fdiv_rn(c, scale));
        q = fminf(fmaxf(q, -127.f), 127.f);
        qb[tid + j * 256] = __float2bfloat16(q);
    }
}

// ---------------- embedding ----------------
__global__ void embed_kernel(const int* __restrict__ idx, const float* __restrict__ emb)
{
    int i = blockIdx.x * blockDim.x + threadIdx.x;
    int s = i >> 10, d = i & 1023;
    g_x[i] = emb[(size_t)idx[s] * D_ + d];
}

// ---------------- rmsnorm ----------------
__global__ void rmsnorm_split_kernel()
{
    int row = blockIdx.x;
    const float* xr = g_x + (size_t)row * D_;
    int tid = threadIdx.x;
    float ss = 0.f;
    for (int i = tid; i < D_; i += 256) { float v = xr[i]; ss += v * v; }
    __shared__ float sh[256];
    sh[tid] = ss; __syncthreads();
    for (int o = 128; o; o >>= 1) {
        if (tid < o) sh[tid] += sh[tid + o];
        __syncthreads();
    }
    float r = rsqrtf(sh[0] / (float)D_ + EPS_);
    for (int i = tid; i < D_; i += 256) {
        split_store(xr[i] * r, g_hhi, g_hlo, (size_t)row * D_ + i);
    }
}

// ---------------- per-head RMS + RoPE + gain (q pre-scaled by 1/8) ----------------
__global__ void qkpost_kernel(const float* __restrict__ gain, int nh, int off, int isq)
{
    int warp = (blockIdx.x * blockDim.x + threadIdx.x) >> 5;
    int lane = threadIdx.x & 31;
    int s = warp / nh, h = warp % nh;
    if (s >= S_) return;
    const float* base = g_qkv + (size_t)s * QKVD_ + off + h * HD_;
    float e0 = base[lane], e1 = base[lane + 32];
    float ss = e0 * e0 + e1 * e1;
    #pragma unroll
    for (int o = 16; o; o >>= 1) ss += __shfl_xor_sync(0xffffffffu, ss, o);
    float r = rsqrtf(ss * (1.f / 64.f) + EPS_);
    e0 *= r; e1 *= r;
    float inv = (float)exp(-((double)lane / 32.0) * 9.210340371976184);
    float f = (float)s * inv;
    float c  = (float)cos((double)f);
    float sn = (float)sin((double)f);
    float o0 =  e0 * c + e1 * sn;
    float o1 = -e0 * sn + e1 * c;
    if (isq) {
        float g = gain[h] * 0.125f;
        split_store(o0 * g, g_qhi, g_qlo, (size_t)s * D_ + h * HD_ + lane);
        split_store(o1 * g, g_qhi, g_qlo, (size_t)s * D_ + h * HD_ + lane + 32);
    } else {
        split_store(o0, g_khi, g_klo, (size_t)s * KVD_ + h * HD_ + lane);
        split_store(o1, g_khi, g_klo, (size_t)s * KVD_ + h * HD_ + lane + 32);
    }
}

// ---------------- V transpose ----------------
__global__ void vtrans_kernel()
{
    __shared__ float t[32][33];
    int s0 = blockIdx.x * 32, c0 = blockIdx.y * 32;
    int tx = threadIdx.x, ty = threadIdx.y;
    #pragma unroll
    for (int k = 0; k < 32; k += 8)
        t[ty + k][tx] = g_qkv[(size_t)(s0 + ty + k) * QKVD_ + 1280 + c0 + tx];
    __syncthreads();
    #pragma unroll
    for (int k = 0; k < 32; k += 8) {
        float v = t[tx][ty + k];
        split_store(v, g_vthi, g_vtlo, (size_t)(c0 + ty + k) * S_ + s0 + tx);
    }
}

// ---------------- fused flash attention ----------------
#define FA_DSM (16384 + 2 * 32768 + 1024)

__global__ __launch_bounds__(128, 1) void flash_kernel()
{
    int bi = 15 - (int)blockIdx.x;
    int h = blockIdx.y, kvh = h >> 2;
    extern __shared__ char fsm[];
    u32 base = (smem_u32(fsm) + 1023u) & ~1023u;

    int tid = threadIdx.x, lane = tid & 31, w = tid >> 5;
    int tig = lane & 3, grp = lane >> 2;

    for (int id = tid; id < 512; id += 128) {
        int r = id >> 3, ck = id & 7;
        u32 so = sw128((u32)(r * 128 + ck * 16));
        size_t gq = (size_t)(bi * 64 + r) * D_ + h * HD_ + ck * 8;
        cpasync16(base + so, g_qhi + gq);
        cpasync16(base + 8192 + so, g_qlo + gq);
    }
    asm volatile("cp.async.commit_group;");

    #define FA_LOAD(st, jt) do { \
        u32 sb_ = base + 16384 + (u32)(st) * 32768; \
        for (int id_ = tid; id_ < 512; id_ += 128) { \
            int r_ = id_ >> 3, ck_ = id_ & 7; \
            u32 so_ = sw128((u32)(r_ * 128 + ck_ * 16)); \
            size_t gk_ = (size_t)((jt) * 64 + r_) * KVD_ + kvh * HD_ + ck_ * 8; \
            cpasync16(sb_ + so_,         g_khi + gk_); \
            cpasync16(sb_ + 8192 + so_,  g_klo + gk_); \
            size_t gv_ = (size_t)(kvh * 64 + r_) * S_ + (jt) * 64 + ck_ * 8; \
            cpasync16(sb_ + 16384 + so_, g_vthi + gv_); \
            cpasync16(sb_ + 24576 + so_, g_vtlo + gv_); \
        } \
        asm volatile("cp.async.commit_group;"); \
    } while (0)

    int n = bi + 1;
    FA_LOAD(0, 0);

    asm volatile("cp.async.wait_group 1;");
    __syncthreads();
    u32 qh[4][4], ql[4][4];
    #pragma unroll
    for (int kc = 0; kc < 4; kc++) {
        int lr = w * 16 + (lane & 15);
        int ch = kc * 2 + (lane >> 4);
        u32 so = sw128((u32)(lr * 128 + ch * 16));
        ldm_x4(qh[kc][0], qh[kc][1], qh[kc][2], qh[kc][3], base + so);
        ldm_x4(ql[kc][0], ql[kc][1], ql[kc][2], ql[kc][3], base + 8192 + so);
    }

    float o[8][4];
    #pragma unroll
    for (int nd = 0; nd < 8; nd++) { o[nd][0]=0.f; o[nd][1]=0.f; o[nd][2]=0.f; o[nd][3]=0.f; }
    float m0 = -1e30f, m1 = -1e30f, l0 = 0.f, l1 = 0.f;

    for (int jt = 0; jt < n; jt++) {
        if (jt + 1 < n) {
            FA_LOAD((jt + 1) & 1, jt + 1);
            asm volatile("cp.async.wait_group 1;");
        } else {
            asm volatile("cp.async.wait_group 0;");
        }
        __syncthreads();

        u32 kb = base + 16384 + (u32)(jt & 1) * 32768;

        float s[8][4];
        #pragma unroll
        for (int ni = 0; ni < 8; ni++) { s[ni][0]=0.f; s[ni][1]=0.f; s[ni][2]=0.f; s[ni][3]=0.f; }
        #pragma unroll
        for (int kc = 0; kc < 4; kc++) {
            u32 bh[8][2], bl[8][2];
            #pragma unroll
            for (int nj = 0; nj < 4; nj++) {
                int g = lane >> 3;
                int lr = nj * 16 + (((g >> 1) & 1) << 3) + (lane & 7);
                int ch = kc * 2 + (g & 1);
                u32 so = sw128((u32)(lr * 128 + ch * 16));
                u32 r0, r1, r2, r3;
                ldm_x4(r0, r1, r2, r3, kb + so);
                bh[nj * 2][0] = r0; bh[nj * 2][1] = r1;
                bh[nj * 2 + 1][0] = r2; bh[nj * 2 + 1][1] = r3;
                ldm_x4(r0, r1, r2, r3, kb + 8192 + so);
                bl[nj * 2][0] = r0; bl[nj * 2][1] = r1;
                bl[nj * 2 + 1][0] = r2; bl[nj * 2 + 1][1] = r3;
            }
            #pragma unroll
            for (int ni = 0; ni < 8; ni++) {
                mma16816(s[ni], qh[kc], bh[ni]);
                mma16816(s[ni], qh[kc], bl[ni]);
                mma16816(s[ni], ql[kc], bh[ni]);
            }
        }

        if (jt == bi) {
            int ci0 = w * 16 + grp, ci1 = ci0 + 8;
            #pragma unroll
            for (int ni = 0; ni < 8; ni++) {
                int cj = ni * 8 + tig * 2;
                if (cj     > ci0) s[ni][0] = -1e30f;
                if (cj + 1 > ci0) s[ni][1] = -1e30f;
                if (cj     > ci1) s[ni][2] = -1e30f;
                if (cj + 1 > ci1) s[ni][3] = -1e30f;
            }
        }

        float tm0 = -1e30f, tm1 = -1e30f;
        #pragma unroll
        for (int ni = 0; ni < 8; ni++) {
            tm0 = fmaxf(tm0, fmaxf(s[ni][0], s[ni][1]));
            tm1 = fmaxf(tm1, fmaxf(s[ni][2], s[ni][3]));
        }
        tm0 = fmaxf(tm0, __shfl_xor_sync(0xffffffffu, tm0, 1));
        tm0 = fmaxf(tm0, __shfl_xor_sync(0xffffffffu, tm0, 2));
        tm1 = fmaxf(tm1, __shfl_xor_sync(0xffffffffu, tm1, 1));
        tm1 = fmaxf(tm1, __shfl_xor_sync(0xffffffffu, tm1, 2));
        float mn0 = fmaxf(m0, tm0), mn1 = fmaxf(m1, tm1);
        float a0 = expf(m0 - mn0), a1 = expf(m1 - mn1);
        m0 = mn0; m1 = mn1;

        float rs0 = 0.f, rs1 = 0.f;
        #pragma unroll
        for (int ni = 0; ni < 8; ni++) {
            s[ni][0] = expf(s[ni][0] - mn0);
            s[ni][1] = expf(s[ni][1] - mn0);
            s[ni][2] = expf(s[ni][2] - mn1);
            s[ni][3] = expf(s[ni][3] - mn1);
            rs0 += s[ni][0] + s[ni][1];
            rs1 += s[ni][2] + s[ni][3];
        }
        rs0 += __shfl_xor_sync(0xffffffffu, rs0, 1);
        rs0 += __shfl_xor_sync(0xffffffffu, rs0, 2);
        rs1 += __shfl_xor_sync(0xffffffffu, rs1, 1);
        rs1 += __shfl_xor_sync(0xffffffffu, rs1, 2);
        l0 = l0 * a0 + rs0;
        l1 = l1 * a1 + rs1;
        #pragma unroll
        for (int nd = 0; nd < 8; nd++) {
            o[nd][0] *= a0; o[nd][1] *= a0;
            o[nd][2] *= a1; o[nd][3] *= a1;
        }

        u32 vbh = kb + 16384, vbl = kb + 24576;
        #pragma unroll
        for (int kc = 0; kc < 4; kc++) {
            u32 pah[4], pal[4];
            split2(s[2 * kc][0],     s[2 * kc][1],     pah[0], pal[0]);
            split2(s[2 * kc][2],     s[2 * kc][3],     pah[1], pal[1]);
            split2(s[2 * kc + 1][0], s[2 * kc + 1][1], pah[2], pal[2]);
            split2(s[2 * kc + 1][2], s[2 * kc + 1][3], pah[3], pal[3]);
            u32 vh[8][2], vl[8][2];
            #pragma unroll
            for (int nj = 0; nj < 4; nj++) {
                int g = lane >> 3;
                int lr = nj * 16 + (((g >> 1) & 1) << 3) + (lane & 7);
                int ch = kc * 2 + (g & 1);
                u32 so = sw128((u32)(lr * 128 + ch * 16));
                u32 r0, r1, r2, r3;
                ldm_x4(r0, r1, r2, r3, vbh + so);
                vh[nj * 2][0] = r0; vh[nj * 2][1] = r1;
                vh[nj * 2 + 1][0] = r2; vh[nj * 2 + 1][1] = r3;
                ldm_x4(r0, r1, r2, r3, vbl + so);
                vl[nj * 2][0] = r0; vl[nj * 2][1] = r1;
                vl[nj * 2 + 1][0] = r2; vl[nj * 2 + 1][1] = r3;
            }
            #pragma unroll
            for (int nd = 0; nd < 8; nd++) {
                mma16816(o[nd], pah, vh[nd]);
                mma16816(o[nd], pah, vl[nd]);
                mma16816(o[nd], pal, vh[nd]);
            }
        }
        __syncthreads();
    }

    float inv0 = 1.0f / l0, inv1 = 1.0f / l1;
    int gi0 = bi * 64 + w * 16 + grp;
    #pragma unroll
    for (int nd = 0; nd < 8; nd++) {
        int gd = h * HD_ + nd * 8 + tig * 2;
        split_store(o[nd][0] * inv0, g_atthi, g_attlo, (size_t)gi0 * D_ + gd);
        split_store(o[nd][1] * inv0, g_atthi, g_attlo, (size_t)gi0 * D_ + gd + 1);
        split_store(o[nd][2] * inv1, g_atthi, g_attlo, (size_t)(gi0 + 8) * D_ + gd);
        split_store(o[nd][3] * inv1, g_atthi, g_attlo, (size_t)(gi0 + 8) * D_ + gd + 1);
    }
    #undef FA_LOAD
}

// ---------------- shared GEMM pieces ----------------
template<int BM, int BN>
__device__ __forceinline__ void load_stage64(
    const __nv_bfloat16* Ahi, const __nv_bfloat16* Alo, const __nv_bfloat16* Bq,
    u32 sbase, int row0, int col0, int K, int k0, int tid)
{
    constexpr u32 ABYTES = (u32)BM * 128;
    for (int id = tid; id < BM * 8; id += 256) {
        int r = id >> 3, ck = id & 7;
        u32 so = sw128((u32)(r * 128 + ck * 16));
        size_t g = (size_t)(row0 + r) * K + k0 + ck * 8;
        cpasync16(sbase + so, Ahi + g);
        cpasync16(sbase + ABYTES + so, Alo + g);
    }
    for (int id = tid; id < BN * 8; id += 256) {
        int r = id >> 3, ck = id & 7;
        u32 so = sw128((u32)(r * 128 + ck * 16));
        cpasync16(sbase + 2 * ABYTES + so, Bq + (size_t)(col0 + r) * K + k0 + ck * 8);
    }
    asm volatile("cp.async.commit_group;");
}

// epilogue dispatch: 0 = g_qkv, 1 = residual into g_x, 2 = relu^2 split into g_ff, 3 = Cout
template<int EPI>
__device__ __forceinline__ void epi_store(float v, int gr, int c, float* Cout, int ldc)
{
    if (EPI == 0) {
        g_qkv[(size_t)gr * QKVD_ + c] = v;
    } else if (EPI == 1) {
        g_x[(size_t)gr * D_ + c] += v;
    } else if (EPI == 2) {
        float t = fmaxf(v, 0.f);
        split_store(t * t, g_ffhi, g_fflo, (size_t)gr * FF_ + c);
    } else {
        Cout[(size_t)gr * ldc + c] = v;
    }
}

// ---------------- small GEMM: 128x64, 2-stage, 2 CTAs/SM ----------------
template<int EPI, int WSEL, int ASEL>
__global__ __launch_bounds__(256, 2)
void qgemm2_kernel(float* __restrict__ Cout, int layer, int N, int K, int ldc)
{
    constexpr int BM = 128, BN = 64;
    constexpr int MI = 2, NI = 4;          // WM=4, WN=2 -> TM=32, TN=32
    constexpr u32 STB = (u32)(2 * BM + BN) * 128;   // 40960

    extern __shared__ char dsm[];
    u32 base = (smem_u32(dsm) + 1023u) & ~1023u;

    int tid = threadIdx.x, lane = tid & 31, wid = tid >> 5;
    int wm = wid % 4, wn = wid / 4;
    int row0 = blockIdx.y * BM, col0 = blockIdx.x * BN;

    const __nv_bfloat16* Ahi = ahisel<ASEL>();
    const __nv_bfloat16* Alo = alosel<ASEL>();
    const __nv_bfloat16* Bq  = qsel<WSEL>() + (size_t)layer * N * K;
    const float* Sc = scsel<WSEL>() + (size_t)layer * N;

    float acc[MI][NI][4];
    #pragma unroll
    for (int mi = 0; mi < MI; mi++)
        #pragma unroll
        for (int ni = 0; ni < NI; ni++) {
            acc[mi][ni][0] = 0.f; acc[mi][ni][1] = 0.f;
            acc[mi][ni][2] = 0.f; acc[mi][ni][3] = 0.f;
        }

    int n = K >> 6;
    load_stage64<BM, BN>(Ahi, Alo, Bq, base,       row0, col0, K, 0,  tid);
    load_stage64<BM, BN>(Ahi, Alo, Bq, base + STB, row0, col0, K, 64, tid);

    for (int it = 0; it < n; it++) {
        if (it + 1 < n) { asm volatile("cp.async.wait_group 1;"); }
        else            { asm volatile("cp.async.wait_group 0;"); }
        __syncthreads();

        u32 sb = base + (u32)(it & 1) * STB;
        #pragma unroll
        for (int kc = 0; kc < 4; kc++) {
            u32 ah[MI][4], al[MI][4];
            #pragma unroll
            for (int mi = 0; mi < MI; mi++) {
                int lr = wm * 32 + mi * 16 + (lane & 15);
                int ch = kc * 2 + (lane >> 4);
                u32 so = sw128((u32)(lr * 128 + ch * 16));
                ldm_x4(ah[mi][0], ah[mi][1], ah[mi][2], ah[mi][3], sb + so);
                ldm_x4(al[mi][0], al[mi][1], al[mi][2], al[mi][3], sb + (u32)BM * 128 + so);
            }
            u32 bb[NI][2];
            #pragma unroll
            for (int nj = 0; nj < NI / 2; nj++) {
                int g = lane >> 3;
                int lr = wn * 32 + nj * 16 + (((g >> 1) & 1) << 3) + (lane & 7);
                int ch = kc * 2 + (g & 1);
                u32 r0, r1, r2, r3;
                ldm_x4(r0, r1, r2, r3, sb + 2u * BM * 128 + sw128((u32)(lr * 128 + ch * 16)));
                bb[nj * 2][0] = r0; bb[nj * 2][1] = r1;
                bb[nj * 2 + 1][0] = r2; bb[nj * 2 + 1][1] = r3;
            }
            #pragma unroll
            for (int mi = 0; mi < MI; mi++)
                #pragma unroll
                for (int ni = 0; ni < NI; ni++) {
                    mma16816(acc[mi][ni], ah[mi], bb[ni]);
                    mma16816(acc[mi][ni], al[mi], bb[ni]);
                }
        }
        __syncthreads();
        if (it + 2 < n)
            load_stage64<BM, BN>(Ahi, Alo, Bq, base + (u32)(it & 1) * STB,
                                 row0, col0, K, (it + 2) << 6, tid);
    }

    #pragma unroll
    for (int mi = 0; mi < MI; mi++) {
        #pragma unroll
        for (int ni = 0; ni < NI; ni++) {
            int gr0 = row0 + wm * 32 + mi * 16 + (lane >> 2);
            int gc  = col0 + wn * 32 + ni * 8 + ((lane & 3) << 1);
            #pragma unroll
            for (int half = 0; half < 2; half++) {
                int gr = gr0 + half * 8;
                #pragma unroll
                for (int e = 0; e < 2; e++) {
                    int c = gc + e;
                    if (c >= N) continue;
                    epi_store<EPI>(acc[mi][ni][half * 2 + e] * Sc[c], gr, c, Cout, ldc);
                }
            }
        }
    }
}

// ---------------- big GEMM: 128x128, 3-stage ----------------
template<int EPI, int WSEL, int ASEL>
__global__ __launch_bounds__(256, 1)
void qgemm3_kernel(float* __restrict__ Cout, int layer, int N, int K, int ldc)
{
    constexpr int BM = 128, BN = 128;
    constexpr int MI = 4, NI = 4;          // WM=2, WN=4 -> TM=64, TN=32
    constexpr u32 STB = (u32)(2 * BM + BN) * 128;   // 49152

    extern __shared__ char dsm[];
    u32 base = (smem_u32(dsm) + 1023u) & ~1023u;

    int tid = threadIdx.x, lane = tid & 31, wid = tid >> 5;
    int wm = wid % 2, wn = wid / 2;
    int row0 = blockIdx.y * BM, col0 = blockIdx.x * BN;

    const __nv_bfloat16* Ahi = ahisel<ASEL>();
    const __nv_bfloat16* Alo = alosel<ASEL>();
    const __nv_bfloat16* Bq  = qsel<WSEL>() + (size_t)layer * N * K;
    const float* Sc = scsel<WSEL>() + (size_t)layer * N;

    float acc[MI][NI][4];
    #pragma unroll
    for (int mi = 0; mi < MI; mi++)
        #pragma unroll
        for (int ni = 0; ni < NI; ni++) {
            acc[mi][ni][0] = 0.f; acc[mi][ni][1] = 0.f;
            acc[mi][ni][2] = 0.f; acc[mi][ni][3] = 0.f;
        }

    int n = K >> 6;
    load_stage64<BM, BN>(Ahi, Alo, Bq, base,       row0, col0, K, 0,  tid);
    load_stage64<BM, BN>(Ahi, Alo, Bq, base + STB, row0, col0, K, 64, tid);

    for (int it = 0; it < n; it++) {
        asm volatile("cp.async.wait_group 1;");
        __syncthreads();

        int ldst = it + 2;
        if (ldst < n) {
            load_stage64<BM, BN>(Ahi, Alo, Bq, base + (u32)(ldst % 3) * STB,
                                 row0, col0, K, ldst << 6, tid);
        } else {
            asm volatile("cp.async.commit_group;");
        }

        u32 sb = base + (u32)(it % 3) * STB;
        #pragma unroll
        for (int kc = 0; kc < 4; kc++) {
            u32 ah[MI][4], al[MI][4];
            #pragma unroll
            for (int mi = 0; mi < MI; mi++) {
                int lr = wm * 64 + mi * 16 + (lane & 15);
                int ch = kc * 2 + (lane >> 4);
                u32 so = sw128((u32)(lr * 128 + ch * 16));
                ldm_x4(ah[mi][0], ah[mi][1], ah[mi][2], ah[mi][3], sb + so);
                ldm_x4(al[mi][0], al[mi][1], al[mi][2], al[mi][3], sb + (u32)BM * 128 + so);
            }
            u32 bb[NI][2];
            #pragma unroll
            for (int nj = 0; nj < NI / 2; nj++) {
                int g = lane >> 3;
                int lr = wn * 32 + nj * 16 + (((g >> 1) & 1) << 3) + (lane & 7);
                int ch = kc * 2 + (g & 1);
                u32 r0, r1, r2, r3;
                ldm_x4(r0, r1, r2, r3, sb + 2u * BM * 128 + sw128((u32)(lr * 128 + ch * 16)));
                bb[nj * 2][0] = r0; bb[nj * 2][1] = r1;
                bb[nj * 2 + 1][0] = r2; bb[nj * 2 + 1][1] = r3;
            }
            #pragma unroll
            for (int mi = 0; mi < MI; mi++)
                #pragma unroll
                for (int ni = 0; ni < NI; ni++) {
                    mma16816(acc[mi][ni], ah[mi], bb[ni]);
                    mma16816(acc[mi][ni], al[mi], bb[ni]);
                }
        }
    }

    #pragma unroll
    for (int mi = 0; mi < MI; mi++) {
        #pragma unroll
        for (int ni = 0; ni < NI; ni++) {
            int gr0 = row0 + wm * 64 + mi * 16 + (lane >> 2);
            int gc  = col0 + wn * 32 + ni * 8 + ((lane & 3) << 1);
            #pragma unroll
            for (int half = 0; half < 2; half++) {
                int gr = gr0 + half * 8;
                #pragma unroll
                for (int e = 0; e < 2; e++) {
                    int c = gc + e;
                    if (c >= N) continue;
                    epi_store<EPI>(acc[mi][ni][half * 2 + e] * Sc[c], gr, c, Cout, ldc);
                }
            }
        }
    }
}

#define DSM_SMALL (2 * (2 * 128 + 64)  * 128 + 1024)
#define DSM_BIG   (3 * (2 * 128 + 128) * 128 + 1024)

// ---------------- host orchestration ----------------
extern "C" void kernel_launch(void* const* d_in, const int* in_sizes, int n_in,
                              void* d_out, int out_size)
{
    (void)in_sizes; (void)n_in; (void)out_size;
    const int*   idx = (const int*)  d_in[0];
    const float* emb = (const float*)d_in[1];
    const float* wq  = (const float*)d_in[2];
    const float* wk  = (const float*)d_in[3];
    const float* wv  = (const float*)d_in[4];
    const float* wo  = (const float*)d_in[5];
    const float* qg  = (const float*)d_in[6];
    const float* wfc = (const float*)d_in[7];
    const float* wpr = (const float*)d_in[8];
    const float* lm  = (const float*)d_in[9];
    float* out = (float*)d_out;

    cudaFuncSetAttribute(qgemm2_kernel<0, 0, 0>,
                         cudaFuncAttributeMaxDynamicSharedMemorySize, DSM_SMALL);
    cudaFuncSetAttribute(qgemm2_kernel<1, 1, 1>,
                         cudaFuncAttributeMaxDynamicSharedMemorySize, DSM_SMALL);
    cudaFuncSetAttribute(qgemm2_kernel<1, 3, 2>,
                         cudaFuncAttributeMaxDynamicSharedMemorySize, DSM_SMALL);
    cudaFuncSetAttribute(qgemm3_kernel<2, 2, 0>,
                         cudaFuncAttributeMaxDynamicSharedMemorySize, DSM_BIG);
    cudaFuncSetAttribute(qgemm3_kernel<3, 4, 0>,
                         cudaFuncAttributeMaxDynamicSharedMemorySize, DSM_BIG);
    cudaFuncSetAttribute(flash_kernel,
                         cudaFuncAttributeMaxDynamicSharedMemorySize, FA_DSM);

    quant_kernel<0, 4><<<L_ * D_,    256>>>(wq,  D_,   QKVD_, 0);
    quant_kernel<0, 4><<<L_ * KVD_,  256>>>(wk,  KVD_, QKVD_, 1024);
    quant_kernel<0, 4><<<L_ * KVD_,  256>>>(wv,  KVD_, QKVD_, 1280);
    quant_kernel<1, 4><<<L_ * D_,    256>>>(wo,  L_ * D_,  0, 0);
    quant_kernel<2, 4><<<L_ * FF_,   256>>>(wfc, L_ * FF_, 0, 0);
    quant_kernel<3, 16><<<L_ * D_,   256>>>(wpr, L_ * D_,  0, 0);
    quant_kernel<4, 4><<<V_,         256>>>(lm,  V_,       0, 0);

    embed_kernel<<<(S_ * D_) / 256, 256>>>(idx, emb);

    for (int l = 0; l < L_; l++) {
        rmsnorm_split_kernel<<<S_, 256>>>();

        qgemm2_kernel<0, 0, 0><<<dim3(QKVD_ / 64, S_ / 128), 256, DSM_SMALL>>>(
            nullptr, l, QKVD_, D_, QKVD_);

        qkpost_kernel<<<(S_ * H_)  / 4, 128>>>(qg + l * H_, H_,  0,    1);
        qkpost_kernel<<<(S_ * KV_) / 4, 128>>>(nullptr,     KV_, 1024, 0);
        vtrans_kernel<<<dim3(S_ / 32, KVD_ / 32), dim3(32, 8)>>>();

        flash_kernel<<<dim3(16, H_), 128, FA_DSM>>>();

        qgemm2_kernel<1, 1, 1><<<dim3(D_ / 64, S_ / 128), 256, DSM_SMALL>>>(
            nullptr, l, D_, D_, D_);

        rmsnorm_split_kernel<<<S_, 256>>>();

        qgemm3_kernel<2, 2, 0><<<dim3(FF_ / 128, S_ / 128), 256, DSM_BIG>>>(
            nullptr, l, FF_, D_, FF_);

        qgemm2_kernel<1, 3, 2><<<dim3(D_ / 64, S_ / 128), 256, DSM_SMALL>>>(
            nullptr, l, D_, FF_, D_);
    }

    rmsnorm_split_kernel<<<S_, 256>>>();
    qgemm3_kernel<3, 4, 0><<<dim3(VPAD_ / 128, S_ / 128), 256, DSM_BIG>>>(
        out, 0, V_, D_, V_);
}

// round 13
// speedup vs baseline: 1.8360x; 1.0018x over previous
#include <cuda_runtime.h>
#include <cuda_fp16.h>
#include <cuda_bf16.h>
#include <stdint.h>
#include <cstdint>
#include <math.h>
#include <float.h>

typedef unsigned int u32;

#define S_   1024
#define D_   1024
#define H_   16
#define KV_  4
#define HD_  64
#define KVD_ 256
#define FF_  4096
#define L_   8
#define V_   50257
#define VPAD_ 50304
#define QKVD_ 1536
#define EPS_ 1.1920928955078125e-07f

// ---------------- device globals ----------------
__device__ __nv_bfloat16 g_qw  [L_ * QKVD_ * D_];
__device__ __nv_bfloat16 g_qwo [L_ * D_   * D_ ];
__device__ __nv_bfloat16 g_qwfc[L_ * FF_  * D_ ];
__device__ __nv_bfloat16 g_qwpr[L_ * D_   * FF_];
__device__ __nv_bfloat16 g_qlm [(size_t)VPAD_ * D_];
__device__ float g_sqkv[L_ * QKVD_];
__device__ float g_swo [L_ * D_ ];
__device__ float g_swfc[L_ * FF_];
__device__ float g_swpr[L_ * D_ ];
__device__ float g_slm [VPAD_];

__device__ float g_x  [S_ * D_ ];
__device__ __nv_bfloat16 g_hhi[S_ * D_ ];
__device__ __nv_bfloat16 g_hlo[S_ * D_ ];
__device__ float g_qkv[S_ * QKVD_];
__device__ __nv_bfloat16 g_atthi[S_ * D_];
__device__ __nv_bfloat16 g_attlo[S_ * D_];
__device__ __nv_bfloat16 g_ffhi [S_ * FF_];
__device__ __nv_bfloat16 g_fflo [S_ * FF_];

__device__ __nv_bfloat16 g_qhi [S_ * D_ ];
__device__ __nv_bfloat16 g_qlo [S_ * D_ ];
__device__ __nv_bfloat16 g_khi [S_ * KVD_];
__device__ __nv_bfloat16 g_klo [S_ * KVD_];
__device__ __nv_bfloat16 g_vthi[KVD_ * S_];
__device__ __nv_bfloat16 g_vtlo[KVD_ * S_];

// ---------------- helpers ----------------
__device__ __forceinline__ u32 smem_u32(const void* p) {
    return (u32)__cvta_generic_to_shared(p);
}
__device__ __forceinline__ void cpasync16(u32 dst, const void* src) {
    asm volatile("cp.async.cg.shared.global [%0], [%1], 16;" :: "r"(dst), "l"(src));
}
__device__ __forceinline__ void ldm_x4(u32& r0, u32& r1, u32& r2, u32& r3, u32 a) {
    asm volatile("ldmatrix.sync.aligned.m8n8.x4.shared.b16 {%0,%1,%2,%3}, [%4];"
        : "=r"(r0), "=r"(r1), "=r"(r2), "=r"(r3) : "r"(a));
}
__device__ __forceinline__ void mma16816(float* d, const u32* a, const u32* b) {
    asm volatile("mma.sync.aligned.m16n8k16.row.col.f32.bf16.bf16.f32 "
        "{%0,%1,%2,%3}, {%4,%5,%6,%7}, {%8,%9}, {%0,%1,%2,%3};"
        : "+f"(d[0]), "+f"(d[1]), "+f"(d[2]), "+f"(d[3])
        : "r"(a[0]), "r"(a[1]), "r"(a[2]), "r"(a[3]), "r"(b[0]), "r"(b[1]));
}
__device__ __forceinline__ u32 sw128(u32 b) {              // 128B rows
    return b ^ ((b >> 3) & 0x70u);
}
__device__ __forceinline__ void split_store(float v, __nv_bfloat16* hi, __nv_bfloat16* lo, size_t i) {
    __nv_bfloat16 h = __float2bfloat16(v);
    hi[i] = h;
    lo[i] = __float2bfloat16(v - __bfloat162float(h));
}
__device__ __forceinline__ void split2(float a, float b, u32& hi, u32& lo) {
    __nv_bfloat16 ha = __float2bfloat16(a), hb = __float2bfloat16(b);
    hi = (u32)__bfloat16_as_ushort(ha) | ((u32)__bfloat16_as_ushort(hb) << 16);
    lo = (u32)__bfloat16_as_ushort(__float2bfloat16(a - __bfloat162float(ha)))
       | ((u32)__bfloat16_as_ushort(__float2bfloat16(b - __bfloat162float(hb))) << 16);
}

template<int W> __device__ __forceinline__ __nv_bfloat16* qsel() {
    if (W == 0) return g_qw;
    if (W == 1) return g_qwo;
    if (W == 2) return g_qwfc;
    if (W == 3) return g_qwpr;
    return g_qlm;
}
template<int W> __device__ __forceinline__ float* scsel() {
    if (W == 0) return g_sqkv;
    if (W == 1) return g_swo;
    if (W == 2) return g_swfc;
    if (W == 3) return g_swpr;
    return g_slm;
}
template<int A> __device__ __forceinline__ const __nv_bfloat16* ahisel() {
    if (A == 0) return g_hhi;
    if (A == 1) return g_atthi;
    return g_ffhi;
}
template<int A> __device__ __forceinline__ const __nv_bfloat16* alosel() {
    if (A == 0) return g_hlo;
    if (A == 1) return g_attlo;
    return g_fflo;
}

// ---------------- fake-quant ----------------
template<int WSEL, int NR>
__global__ void quant_kernel(const float* __restrict__ W, int rpl, int ld, int off)
{
    const int n = NR * 256;
    int blk = blockIdx.x;
    int l = blk / rpl, r = blk % rpl;
    int out_row = l * ld + off + r;
    const float* w = W + (size_t)blk * n;
    __nv_bfloat16* qb = qsel<WSEL>() + (size_t)out_row * n;
    int tid = threadIdx.x;

    float v[NR];
    float m1 = 0.f, m2 = 0.f;
    #pragma unroll
    for (int j = 0; j < NR; j++) {
        v[j] = w[tid + j * 256];
        float a = fabsf(v[j]);
        if (a > m1) { m2 = m1; m1 = a; }
        else if (a > m2) { m2 = a; }
    }
    __shared__ float s1[256], s2[256];
    s1[tid] = m1; s2[tid] = m2;
    __syncthreads();
    for (int o = 128; o; o >>= 1) {
        if (tid < o) {
            float a1 = s1[tid], a2 = s2[tid];
            float b1 = s1[tid + o], b2 = s2[tid + o];
            s1[tid] = fmaxf(a1, b1);
            s2[tid] = fmaxf(fminf(a1, b1), fmaxf(a2, b2));
        }
        __syncthreads();
    }
    __shared__ float sh_clip, sh_scale;
    if (tid == 0) {
        float M1 = s1[0], M2 = s2[0];
        float idxf = 0.9999984f * (float)(n - 1);
        float frac = idxf - (float)(n - 2);
        float clip = M2 * (1.0f - frac) + M1 * frac;
        float scale = fmaxf(__fdiv_rn(clip, 127.0f), 1.0f / 127.0f);
        sh_clip = clip;
        sh_scale = scale;
        scsel<WSEL>()[out_row] = __half2float(__float2half_rn(scale));
    }
    __syncthreads();
    float clip = sh_clip, scale = sh_scale;
    #pragma unroll
    for (int j = 0; j < NR; j++) {
        float c = fminf(fmaxf(v[j], -clip), clip);
        float q = rintf(__fdiv_rn(c, scale));
        q = fminf(fmaxf(q, -127.f), 127.f);
        qb[tid + j * 256] = __float2bfloat16(q);
    }
}

// ---------------- embedding ----------------
__global__ void embed_kernel(const int* __restrict__ idx, const float* __restrict__ emb)
{
    int i = blockIdx.x * blockDim.x + threadIdx.x;
    int s = i >> 10, d = i & 1023;
    g_x[i] = emb[(size_t)idx[s] * D_ + d];
}

// ---------------- rmsnorm ----------------
__global__ void rmsnorm_split_kernel()
{
    int row = blockIdx.x;
    const float* xr = g_x + (size_t)row * D_;
    int tid = threadIdx.x;
    float ss = 0.f;
    for (int i = tid; i < D_; i += 256) { float v = xr[i]; ss += v * v; }
    __shared__ float sh[256];
    sh[tid] = ss; __syncthreads();
    for (int o = 128; o; o >>= 1) {
        if (tid < o) sh[tid] += sh[tid + o];
        __syncthreads();
    }
    float r = rsqrtf(sh[0] / (float)D_ + EPS_);
    for (int i = tid; i < D_; i += 256) {
        split_store(xr[i] * r, g_hhi, g_hlo, (size_t)row * D_ + i);
    }
}

// ---------------- merged per-head RMS + RoPE + gain (q and k in one launch) ----------------
__global__ void qkpost_kernel(const float* __restrict__ gain)
{
    int warp = (blockIdx.x * blockDim.x + threadIdx.x) >> 5;
    int lane = threadIdx.x & 31;
    int s = warp / 20, j = warp % 20;
    if (s >= S_) return;
    int isq = (j < 16);
    int h = isq ? j : j - 16;
    int off = isq ? 0 : 1024;
    const float* base = g_qkv + (size_t)s * QKVD_ + off + h * HD_;
    float e0 = base[lane], e1 = base[lane + 32];
    float ss = e0 * e0 + e1 * e1;
    #pragma unroll
    for (int o = 16; o; o >>= 1) ss += __shfl_xor_sync(0xffffffffu, ss, o);
    float r = rsqrtf(ss * (1.f / 64.f) + EPS_);
    e0 *= r; e1 *= r;
    float inv = (float)exp(-((double)lane / 32.0) * 9.210340371976184);
    float f = (float)s * inv;
    float c  = (float)cos((double)f);
    float sn = (float)sin((double)f);
    float o0 =  e0 * c + e1 * sn;
    float o1 = -e0 * sn + e1 * c;
    if (isq) {
        float g = gain[h] * 0.125f;
        split_store(o0 * g, g_qhi, g_qlo, (size_t)s * D_ + h * HD_ + lane);
        split_store(o1 * g, g_qhi, g_qlo, (size_t)s * D_ + h * HD_ + lane + 32);
    } else {
        split_store(o0, g_khi, g_klo, (size_t)s * KVD_ + h * HD_ + lane);
        split_store(o1, g_khi, g_klo, (size_t)s * KVD_ + h * HD_ + lane + 32);
    }
}

// ---------------- V transpose ----------------
__global__ void vtrans_kernel()
{
    __shared__ float t[32][33];
    int s0 = blockIdx.x * 32, c0 = blockIdx.y * 32;
    int tx = threadIdx.x, ty = threadIdx.y;
    #pragma unroll
    for (int k = 0; k < 32; k += 8)
        t[ty + k][tx] = g_qkv[(size_t)(s0 + ty + k) * QKVD_ + 1280 + c0 + tx];
    __syncthreads();
    #pragma unroll
    for (int k = 0; k < 32; k += 8) {
        float v = t[tx][ty + k];
        split_store(v, g_vthi, g_vtlo, (size_t)(c0 + ty + k) * S_ + s0 + tx);
    }
}

// ---------------- fused flash attention: 128-row Q tiles, 256 threads ----------------
#define FA_DSM (32768 + 2 * 32768 + 1024)

__global__ __launch_bounds__(256, 1) void flash_kernel()
{
    int bi = 7 - (int)blockIdx.x;       // longest blocks first
    int h = blockIdx.y, kvh = h >> 2;
    extern __shared__ char fsm[];
    u32 base = (smem_u32(fsm) + 1023u) & ~1023u;

    int tid = threadIdx.x, lane = tid & 31, w = tid >> 5;
    int tig = lane & 3, grp = lane >> 2;

    // Q tile: 128 rows, hi @ base, lo @ base+16384
    for (int id = tid; id < 1024; id += 256) {
        int r = id >> 3, ck = id & 7;
        u32 so = sw128((u32)(r * 128 + ck * 16));
        size_t gq = (size_t)(bi * 128 + r) * D_ + h * HD_ + ck * 8;
        cpasync16(base + so, g_qhi + gq);
        cpasync16(base + 16384 + so, g_qlo + gq);
    }
    asm volatile("cp.async.commit_group;");

    #define FA_LOAD(st, jt) do { \
        u32 sb_ = base + 32768 + (u32)(st) * 32768; \
        for (int id_ = tid; id_ < 512; id_ += 256) { \
            int r_ = id_ >> 3, ck_ = id_ & 7; \
            u32 so_ = sw128((u32)(r_ * 128 + ck_ * 16)); \
            size_t gk_ = (size_t)((jt) * 64 + r_) * KVD_ + kvh * HD_ + ck_ * 8; \
            cpasync16(sb_ + so_,         g_khi + gk_); \
            cpasync16(sb_ + 8192 + so_,  g_klo + gk_); \
            size_t gv_ = (size_t)(kvh * 64 + r_) * S_ + (jt) * 64 + ck_ * 8; \
            cpasync16(sb_ + 16384 + so_, g_vthi + gv_); \
            cpasync16(sb_ + 24576 + so_, g_vtlo + gv_); \
        } \
        asm volatile("cp.async.commit_group;"); \
    } while (0)

    int n = 2 * bi + 2;
    FA_LOAD(0, 0);

    asm volatile("cp.async.wait_group 1;");
    __syncthreads();
    u32 qh[4][4], ql[4][4];
    #pragma unroll
    for (int kc = 0; kc < 4; kc++) {
        int lr = w * 16 + (lane & 15);
        int ch = kc * 2 + (lane >> 4);
        u32 so = sw128((u32)(lr * 128 + ch * 16));
        ldm_x4(qh[kc][0], qh[kc][1], qh[kc][2], qh[kc][3], base + so);
        ldm_x4(ql[kc][0], ql[kc][1], ql[kc][2], ql[kc][3], base + 16384 + so);
    }

    float o[8][4];
    #pragma unroll
    for (int nd = 0; nd < 8; nd++) { o[nd][0]=0.f; o[nd][1]=0.f; o[nd][2]=0.f; o[nd][3]=0.f; }
    float m0 = -1e30f, m1 = -1e30f, l0 = 0.f, l1 = 0.f;

    for (int jt = 0; jt < n; jt++) {
        if (jt + 1 < n) {
            FA_LOAD((jt + 1) & 1, jt + 1);
            asm volatile("cp.async.wait_group 1;");
        } else {
            asm volatile("cp.async.wait_group 0;");
        }
        __syncthreads();

        u32 kb = base + 32768 + (u32)(jt & 1) * 32768;

        float s[8][4];
        #pragma unroll
        for (int ni = 0; ni < 8; ni++) { s[ni][0]=0.f; s[ni][1]=0.f; s[ni][2]=0.f; s[ni][3]=0.f; }
        #pragma unroll
        for (int kc = 0; kc < 4; kc++) {
            u32 bh[8][2], bl[8][2];
            #pragma unroll
            for (int nj = 0; nj < 4; nj++) {
                int g = lane >> 3;
                int lr = nj * 16 + (((g >> 1) & 1) << 3) + (lane & 7);
                int ch = kc * 2 + (g & 1);
                u32 so = sw128((u32)(lr * 128 + ch * 16));
                u32 r0, r1, r2, r3;
                ldm_x4(r0, r1, r2, r3, kb + so);
                bh[nj * 2][0] = r0; bh[nj * 2][1] = r1;
                bh[nj * 2 + 1][0] = r2; bh[nj * 2 + 1][1] = r3;
                ldm_x4(r0, r1, r2, r3, kb + 8192 + so);
                bl[nj * 2][0] = r0; bl[nj * 2][1] = r1;
                bl[nj * 2 + 1][0] = r2; bl[nj * 2 + 1][1] = r3;
            }
            #pragma unroll
            for (int ni = 0; ni < 8; ni++) {
                mma16816(s[ni], qh[kc], bh[ni]);
                mma16816(s[ni], qh[kc], bl[ni]);
                mma16816(s[ni], ql[kc], bh[ni]);
            }
        }

        // causal mask (only the last two kv tiles can intersect the diagonal)
        if (jt >= 2 * bi) {
            int ci0 = bi * 128 + w * 16 + grp, ci1 = ci0 + 8;
            #pragma unroll
            for (int ni = 0; ni < 8; ni++) {
                int cj = jt * 64 + ni * 8 + tig * 2;
                if (cj     > ci0) s[ni][0] = -1e30f;
                if (cj + 1 > ci0) s[ni][1] = -1e30f;
                if (cj     > ci1) s[ni][2] = -1e30f;
                if (cj + 1 > ci1) s[ni][3] = -1e30f;
            }
        }

        float tm0 = -1e30f, tm1 = -1e30f;
        #pragma unroll
        for (int ni = 0; ni < 8; ni++) {
            tm0 = fmaxf(tm0, fmaxf(s[ni][0], s[ni][1]));
            tm1 = fmaxf(tm1, fmaxf(s[ni][2], s[ni][3]));
        }
        tm0 = fmaxf(tm0, __shfl_xor_sync(0xffffffffu, tm0, 1));
        tm0 = fmaxf(tm0, __shfl_xor_sync(0xffffffffu, tm0, 2));
        tm1 = fmaxf(tm1, __shfl_xor_sync(0xffffffffu, tm1, 1));
        tm1 = fmaxf(tm1, __shfl_xor_sync(0xffffffffu, tm1, 2));
        float mn0 = fmaxf(m0, tm0), mn1 = fmaxf(m1, tm1);
        float a0 = expf(m0 - mn0), a1 = expf(m1 - mn1);
        m0 = mn0; m1 = mn1;

        float rs0 = 0.f, rs1 = 0.f;
        #pragma unroll
        for (int ni = 0; ni < 8; ni++) {
            s[ni][0] = expf(s[ni][0] - mn0);
            s[ni][1] = expf(s[ni][1] - mn0);
            s[ni][2] = expf(s[ni][2] - mn1);
            s[ni][3] = expf(s[ni][3] - mn1);
            rs0 += s[ni][0] + s[ni][1];
            rs1 += s[ni][2] + s[ni][3];
        }
        rs0 += __shfl_xor_sync(0xffffffffu, rs0, 1);
        rs0 += __shfl_xor_sync(0xffffffffu, rs0, 2);
        rs1 += __shfl_xor_sync(0xffffffffu, rs1, 1);
        rs1 += __shfl_xor_sync(0xffffffffu, rs1, 2);
        l0 = l0 * a0 + rs0;
        l1 = l1 * a1 + rs1;
        #pragma unroll
        for (int nd = 0; nd < 8; nd++) {
            o[nd][0] *= a0; o[nd][1] *= a0;
            o[nd][2] *= a1; o[nd][3] *= a1;
        }

        u32 vbh = kb + 16384, vbl = kb + 24576;
        #pragma unroll
        for (int kc = 0; kc < 4; kc++) {
            u32 pah[4], pal[4];
            split2(s[2 * kc][0],     s[2 * kc][1],     pah[0], pal[0]);
            split2(s[2 * kc][2],     s[2 * kc][3],     pah[1], pal[1]);
            split2(s[2 * kc + 1][0], s[2 * kc + 1][1], pah[2], pal[2]);
            split2(s[2 * kc + 1][2], s[2 * kc + 1][3], pah[3], pal[3]);
            u32 vh[8][2], vl[8][2];
            #pragma unroll
            for (int nj = 0; nj < 4; nj++) {
                int g = lane >> 3;
                int lr = nj * 16 + (((g >> 1) & 1) << 3) + (lane & 7);
                int ch = kc * 2 + (g & 1);
                u32 so = sw128((u32)(lr * 128 + ch * 16));
                u32 r0, r1, r2, r3;
                ldm_x4(r0, r1, r2, r3, vbh + so);
                vh[nj * 2][0] = r0; vh[nj * 2][1] = r1;
                vh[nj * 2 + 1][0] = r2; vh[nj * 2 + 1][1] = r3;
                ldm_x4(r0, r1, r2, r3, vbl + so);
                vl[nj * 2][0] = r0; vl[nj * 2][1] = r1;
                vl[nj * 2 + 1][0] = r2; vl[nj * 2 + 1][1] = r3;
            }
            #pragma unroll
            for (int nd = 0; nd < 8; nd++) {
                mma16816(o[nd], pah, vh[nd]);
                mma16816(o[nd], pah, vl[nd]);
                mma16816(o[nd], pal, vh[nd]);
            }
        }
        __syncthreads();
    }

    float inv0 = 1.0f / l0, inv1 = 1.0f / l1;
    int gi0 = bi * 128 + w * 16 + grp;
    #pragma unroll
    for (int nd = 0; nd < 8; nd++) {
        int gd = h * HD_ + nd * 8 + tig * 2;
        split_store(o[nd][0] * inv0, g_atthi, g_attlo, (size_t)gi0 * D_ + gd);
        split_store(o[nd][1] * inv0, g_atthi, g_attlo, (size_t)gi0 * D_ + gd + 1);
        split_store(o[nd][2] * inv1, g_atthi, g_attlo, (size_t)(gi0 + 8) * D_ + gd);
        split_store(o[nd][3] * inv1, g_atthi, g_attlo, (size_t)(gi0 + 8) * D_ + gd + 1);
    }
    #undef FA_LOAD
}

// ---------------- shared GEMM pieces ----------------
template<int BM, int BN>
__device__ __forceinline__ void load_stage64(
    const __nv_bfloat16* Ahi, const __nv_bfloat16* Alo, const __nv_bfloat16* Bq,
    u32 sbase, int row0, int col0, int K, int k0, int tid)
{
    constexpr u32 ABYTES = (u32)BM * 128;
    for (int id = tid; id < BM * 8; id += 256) {
        int r = id >> 3, ck = id & 7;
        u32 so = sw128((u32)(r * 128 + ck * 16));
        size_t g = (size_t)(row0 + r) * K + k0 + ck * 8;
        cpasync16(sbase + so, Ahi + g);
        cpasync16(sbase + ABYTES + so, Alo + g);
    }
    for (int id = tid; id < BN * 8; id += 256) {
        int r = id >> 3, ck = id & 7;
        u32 so = sw128((u32)(r * 128 + ck * 16));
        cpasync16(sbase + 2 * ABYTES + so, Bq + (size_t)(col0 + r) * K + k0 + ck * 8);
    }
    asm volatile("cp.async.commit_group;");
}

template<int EPI>
__device__ __forceinline__ void epi_store(float v, int gr, int c, float* Cout, int ldc)
{
    if (EPI == 0) {
        g_qkv[(size_t)gr * QKVD_ + c] = v;
    } else if (EPI == 1) {
        g_x[(size_t)gr * D_ + c] += v;
    } else if (EPI == 2) {
        float t = fmaxf(v, 0.f);
        split_store(t * t, g_ffhi, g_fflo, (size_t)gr * FF_ + c);
    } else {
        Cout[(size_t)gr * ldc + c] = v;
    }
}

// ---------------- small GEMM: 128x64, 2-stage, 2 CTAs/SM ----------------
template<int EPI, int WSEL, int ASEL>
__global__ __launch_bounds__(256, 2)
void qgemm2_kernel(float* __restrict__ Cout, int layer, int N, int K, int ldc)
{
    constexpr int BM = 128, BN = 64;
    constexpr int MI = 2, NI = 4;
    constexpr u32 STB = (u32)(2 * BM + BN) * 128;

    extern __shared__ char dsm[];
    u32 base = (smem_u32(dsm) + 1023u) & ~1023u;

    int tid = threadIdx.x, lane = tid & 31, wid = tid >> 5;
    int wm = wid % 4, wn = wid / 4;
    int row0 = blockIdx.y * BM, col0 = blockIdx.x * BN;

    const __nv_bfloat16* Ahi = ahisel<ASEL>();
    const __nv_bfloat16* Alo = alosel<ASEL>();
    const __nv_bfloat16* Bq  = qsel<WSEL>() + (size_t)layer * N * K;
    const float* Sc = scsel<WSEL>() + (size_t)layer * N;

    float acc[MI][NI][4];
    #pragma unroll
    for (int mi = 0; mi < MI; mi++)
        #pragma unroll
        for (int ni = 0; ni < NI; ni++) {
            acc[mi][ni][0] = 0.f; acc[mi][ni][1] = 0.f;
            acc[mi][ni][2] = 0.f; acc[mi][ni][3] = 0.f;
        }

    int n = K >> 6;
    load_stage64<BM, BN>(Ahi, Alo, Bq, base,       row0, col0, K, 0,  tid);
    load_stage64<BM, BN>(Ahi, Alo, Bq, base + STB, row0, col0, K, 64, tid);

    for (int it = 0; it < n; it++) {
        if (it + 1 < n) { asm volatile("cp.async.wait_group 1;"); }
        else            { asm volatile("cp.async.wait_group 0;"); }
        __syncthreads();

        u32 sb = base + (u32)(it & 1) * STB;
        #pragma unroll
        for (int kc = 0; kc < 4; kc++) {
            u32 ah[MI][4], al[MI][4];
            #pragma unroll
            for (int mi = 0; mi < MI; mi++) {
                int lr = wm * 32 + mi * 16 + (lane & 15);
                int ch = kc * 2 + (lane >> 4);
                u32 so = sw128((u32)(lr * 128 + ch * 16));
                ldm_x4(ah[mi][0], ah[mi][1], ah[mi][2], ah[mi][3], sb + so);
                ldm_x4(al[mi][0], al[mi][1], al[mi][2], al[mi][3], sb + (u32)BM * 128 + so);
            }
            u32 bb[NI][2];
            #pragma unroll
            for (int nj = 0; nj < NI / 2; nj++) {
                int g = lane >> 3;
                int lr = wn * 32 + nj * 16 + (((g >> 1) & 1) << 3) + (lane & 7);
                int ch = kc * 2 + (g & 1);
                u32 r0, r1, r2, r3;
                ldm_x4(r0, r1, r2, r3, sb + 2u * BM * 128 + sw128((u32)(lr * 128 + ch * 16)));
                bb[nj * 2][0] = r0; bb[nj * 2][1] = r1;
                bb[nj * 2 + 1][0] = r2; bb[nj * 2 + 1][1] = r3;
            }
            #pragma unroll
            for (int mi = 0; mi < MI; mi++)
                #pragma unroll
                for (int ni = 0; ni < NI; ni++) {
                    mma16816(acc[mi][ni], ah[mi], bb[ni]);
                    mma16816(acc[mi][ni], al[mi], bb[ni]);
                }
        }
        __syncthreads();
        if (it + 2 < n)
            load_stage64<BM, BN>(Ahi, Alo, Bq, base + (u32)(it & 1) * STB,
                                 row0, col0, K, (it + 2) << 6, tid);
    }

    #pragma unroll
    for (int mi = 0; mi < MI; mi++) {
        #pragma unroll
        for (int ni = 0; ni < NI; ni++) {
            int gr0 = row0 + wm * 32 + mi * 16 + (lane >> 2);
            int gc  = col0 + wn * 32 + ni * 8 + ((lane & 3) << 1);
            #pragma unroll
            for (int half = 0; half < 2; half++) {
                int gr = gr0 + half * 8;
                #pragma unroll
                for (int e = 0; e < 2; e++) {
                    int c = gc + e;
                    if (c >= N) continue;
                    epi_store<EPI>(acc[mi][ni][half * 2 + e] * Sc[c], gr, c, Cout, ldc);
                }
            }
        }
    }
}

// ---------------- big GEMM: 128x128, 3-stage ----------------
template<int EPI, int WSEL, int ASEL>
__global__ __launch_bounds__(256, 1)
void qgemm3_kernel(float* __restrict__ Cout, int layer, int N, int K, int ldc)
{
    constexpr int BM = 128, BN = 128;
    constexpr int MI = 4, NI = 4;
    constexpr u32 STB = (u32)(2 * BM + BN) * 128;

    extern __shared__ char dsm[];
    u32 base = (smem_u32(dsm) + 1023u) & ~1023u;

    int tid = threadIdx.x, lane = tid & 31, wid = tid >> 5;
    int wm = wid % 2, wn = wid / 2;
    int row0 = blockIdx.y * BM, col0 = blockIdx.x * BN;

    const __nv_bfloat16* Ahi = ahisel<ASEL>();
    const __nv_bfloat16* Alo = alosel<ASEL>();
    const __nv_bfloat16* Bq  = qsel<WSEL>() + (size_t)layer * N * K;
    const float* Sc = scsel<WSEL>() + (size_t)layer * N;

    float acc[MI][NI][4];
    #pragma unroll
    for (int mi = 0; mi < MI; mi++)
        #pragma unroll
        for (int ni = 0; ni < NI; ni++) {
            acc[mi][ni][0] = 0.f; acc[mi][ni][1] = 0.f;
            acc[mi][ni][2] = 0.f; acc[mi][ni][3] = 0.f;
        }

    int n = K >> 6;
    load_stage64<BM, BN>(Ahi, Alo, Bq, base,       row0, col0, K, 0,  tid);
    load_stage64<BM, BN>(Ahi, Alo, Bq, base + STB, row0, col0, K, 64, tid);

    for (int it = 0; it < n; it++) {
        asm volatile("cp.async.wait_group 1;");
        __syncthreads();

        int ldst = it + 2;
        if (ldst < n) {
            load_stage64<BM, BN>(Ahi, Alo, Bq, base + (u32)(ldst % 3) * STB,
                                 row0, col0, K, ldst << 6, tid);
        } else {
            asm volatile("cp.async.commit_group;");
        }

        u32 sb = base + (u32)(it % 3) * STB;
        #pragma unroll
        for (int kc = 0; kc < 4; kc++) {
            u32 ah[MI][4], al[MI][4];
            #pragma unroll
            for (int mi = 0; mi < MI; mi++) {
                int lr = wm * 64 + mi * 16 + (lane & 15);
                int ch = kc * 2 + (lane >> 4);
                u32 so = sw128((u32)(lr * 128 + ch * 16));
                ldm_x4(ah[mi][0], ah[mi][1], ah[mi][2], ah[mi][3], sb + so);
                ldm_x4(al[mi][0], al[mi][1], al[mi][2], al[mi][3], sb + (u32)BM * 128 + so);
            }
            u32 bb[NI][2];
            #pragma unroll
            for (int nj = 0; nj < NI / 2; nj++) {
                int g = lane >> 3;
                int lr = wn * 32 + nj * 16 + (((g >> 1) & 1) << 3) + (lane & 7);
                int ch = kc * 2 + (g & 1);
                u32 r0, r1, r2, r3;
                ldm_x4(r0, r1, r2, r3, sb + 2u * BM * 128 + sw128((u32)(lr * 128 + ch * 16)));
                bb[nj * 2][0] = r0; bb[nj * 2][1] = r1;
                bb[nj * 2 + 1][0] = r2; bb[nj * 2 + 1][1] = r3;
            }
            #pragma unroll
            for (int mi = 0; mi < MI; mi++)
                #pragma unroll
                for (int ni = 0; ni < NI; ni++) {
                    mma16816(acc[mi][ni], ah[mi], bb[ni]);
                    mma16816(acc[mi][ni], al[mi], bb[ni]);
                }
        }
    }

    #pragma unroll
    for (int mi = 0; mi < MI; mi++) {
        #pragma unroll
        for (int ni = 0; ni < NI; ni++) {
            int gr0 = row0 + wm * 64 + mi * 16 + (lane >> 2);
            int gc  = col0 + wn * 32 + ni * 8 + ((lane & 3) << 1);
            #pragma unroll
            for (int half = 0; half < 2; half++) {
                int gr = gr0 + half * 8;
                #pragma unroll
                for (int e = 0; e < 2; e++) {
                    int c = gc + e;
                    if (c >= N) continue;
                    epi_store<EPI>(acc[mi][ni][half * 2 + e] * Sc[c], gr, c, Cout, ldc);
                }
            }
        }
    }
}

#define DSM_SMALL (2 * (2 * 128 + 64)  * 128 + 1024)
#define DSM_BIG   (3 * (2 * 128 + 128) * 128 + 1024)

// ---------------- host orchestration ----------------
extern "C" void kernel_launch(void* const* d_in, const int* in_sizes, int n_in,
                              void* d_out, int out_size)
{
    (void)in_sizes; (void)n_in; (void)out_size;
    const int*   idx = (const int*)  d_in[0];
    const float* emb = (const float*)d_in[1];
    const float* wq  = (const float*)d_in[2];
    const float* wk  = (const float*)d_in[3];
    const float* wv  = (const float*)d_in[4];
    const float* wo  = (const float*)d_in[5];
    const float* qg  = (const float*)d_in[6];
    const float* wfc = (const float*)d_in[7];
    const float* wpr = (const float*)d_in[8];
    const float* lm  = (const float*)d_in[9];
    float* out = (float*)d_out;

    cudaFuncSetAttribute(qgemm2_kernel<0, 0, 0>,
                         cudaFuncAttributeMaxDynamicSharedMemorySize, DSM_SMALL);
    cudaFuncSetAttribute(qgemm2_kernel<1, 1, 1>,
                         cudaFuncAttributeMaxDynamicSharedMemorySize, DSM_SMALL);
    cudaFuncSetAttribute(qgemm2_kernel<1, 3, 2>,
                         cudaFuncAttributeMaxDynamicSharedMemorySize, DSM_SMALL);
    cudaFuncSetAttribute(qgemm3_kernel<2, 2, 0>,
                         cudaFuncAttributeMaxDynamicSharedMemorySize, DSM_BIG);
    cudaFuncSetAttribute(qgemm3_kernel<3, 4, 0>,
                         cudaFuncAttributeMaxDynamicSharedMemorySize, DSM_BIG);
    cudaFuncSetAttribute(flash_kernel,
                         cudaFuncAttributeMaxDynamicSharedMemorySize, FA_DSM);

    quant_kernel<0, 4><<<L_ * D_,    256>>>(wq,  D_,   QKVD_, 0);
    quant_kernel<0, 4><<<L_ * KVD_,  256>>>(wk,  KVD_, QKVD_, 1024);
    quant_kernel<0, 4><<<L_ * KVD_,  256>>>(wv,  KVD_, QKVD_, 1280);
    quant_kernel<1, 4><<<L_ * D_,    256>>>(wo,  L_ * D_,  0, 0);
    quant_kernel<2, 4><<<L_ * FF_,   256>>>(wfc, L_ * FF_, 0, 0);
    quant_kernel<3, 16><<<L_ * D_,   256>>>(wpr, L_ * D_,  0, 0);
    quant_kernel<4, 4><<<V_,         256>>>(lm,  V_,       0, 0);

    embed_kernel<<<(S_ * D_) / 256, 256>>>(idx, emb);

    for (int l = 0; l < L_; l++) {
        rmsnorm_split_kernel<<<S_, 256>>>();

        qgemm2_kernel<0, 0, 0><<<dim3(QKVD_ / 64, S_ / 128), 256, DSM_SMALL>>>(
            nullptr, l, QKVD_, D_, QKVD_);

        qkpost_kernel<<<(S_ * 20) / 4, 128>>>(qg + l * H_);
        vtrans_kernel<<<dim3(S_ / 32, KVD_ / 32), dim3(32, 8)>>>();

        flash_kernel<<<dim3(8, H_), 256, FA_DSM>>>();

        qgemm2_kernel<1, 1, 1><<<dim3(D_ / 64, S_ / 128), 256, DSM_SMALL>>>(
            nullptr, l, D_, D_, D_);

        rmsnorm_split_kernel<<<S_, 256>>>();

        qgemm3_kernel<2, 2, 0><<<dim3(FF_ / 128, S_ / 128), 256, DSM_BIG>>>(
            nullptr, l, FF_, D_, FF_);

        qgemm2_kernel<1, 3, 2><<<dim3(D_ / 64, S_ / 128), 256, DSM_SMALL>>>(
            nullptr, l, D_, FF_, D_);
    }

    rmsnorm_split_kernel<<<S_, 256>>>();
    qgemm3_kernel<3, 4, 0><<<dim3(VPAD_ / 128, S_ / 128), 256, DSM_BIG>>>(
        out, 0, V_, D_, V_);
}

// round 14
// speedup vs baseline: 1.9355x; 1.0542x over previous
#include <cuda_runtime.h>
#include <cuda_fp16.h>
#include <cuda_bf16.h>
#include <stdint.h>
#include <cstdint>
#include <math.h>
#include <float.h>

typedef unsigned int u32;

#define S_   1024
#define D_   1024
#define H_   16
#define KV_  4
#define HD_  64
#define KVD_ 256
#define FF_  4096
#define L_   8
#define V_   50257
#define VPAD_ 50304
#define QKVD_ 1536
#define EPS_ 1.1920928955078125e-07f

// ---------------- device globals ----------------
__device__ __nv_bfloat16 g_qw  [L_ * QKVD_ * D_];
__device__ __nv_bfloat16 g_qwo [L_ * D_   * D_ ];
__device__ __nv_bfloat16 g_qwfc[L_ * FF_  * D_ ];
__device__ __nv_bfloat16 g_qwpr[L_ * D_   * FF_];
__device__ __half        g_qlmh[(size_t)VPAD_ * D_];   // lm_head weights (fp16, exact ints)
__device__ float g_sqkv[L_ * QKVD_];
__device__ float g_swo [L_ * D_ ];
__device__ float g_swfc[L_ * FF_];
__device__ float g_swpr[L_ * D_ ];
__device__ float g_slm [VPAD_];

__device__ float g_x  [S_ * D_ ];
__device__ __nv_bfloat16 g_hhi[S_ * D_ ];
__device__ __nv_bfloat16 g_hlo[S_ * D_ ];
__device__ __half        g_h16[S_ * D_ ];              // final rmsnorm, fp16
__device__ float g_qkv[S_ * QKVD_];
__device__ __nv_bfloat16 g_atthi[S_ * D_];
__device__ __nv_bfloat16 g_attlo[S_ * D_];
__device__ __nv_bfloat16 g_ffhi [S_ * FF_];
__device__ __nv_bfloat16 g_fflo [S_ * FF_];

__device__ __nv_bfloat16 g_qhi [S_ * D_ ];
__device__ __nv_bfloat16 g_qlo [S_ * D_ ];
__device__ __nv_bfloat16 g_khi [S_ * KVD_];
__device__ __nv_bfloat16 g_klo [S_ * KVD_];
__device__ __nv_bfloat16 g_vthi[KVD_ * S_];
__device__ __nv_bfloat16 g_vtlo[KVD_ * S_];

// ---------------- helpers ----------------
__device__ __forceinline__ u32 smem_u32(const void* p) {
    return (u32)__cvta_generic_to_shared(p);
}
__device__ __forceinline__ void cpasync16(u32 dst, const void* src) {
    asm volatile("cp.async.cg.shared.global [%0], [%1], 16;" :: "r"(dst), "l"(src));
}
__device__ __forceinline__ void ldm_x4(u32& r0, u32& r1, u32& r2, u32& r3, u32 a) {
    asm volatile("ldmatrix.sync.aligned.m8n8.x4.shared.b16 {%0,%1,%2,%3}, [%4];"
        : "=r"(r0), "=r"(r1), "=r"(r2), "=r"(r3) : "r"(a));
}
__device__ __forceinline__ void mma16816(float* d, const u32* a, const u32* b) {
    asm volatile("mma.sync.aligned.m16n8k16.row.col.f32.bf16.bf16.f32 "
        "{%0,%1,%2,%3}, {%4,%5,%6,%7}, {%8,%9}, {%0,%1,%2,%3};"
        : "+f"(d[0]), "+f"(d[1]), "+f"(d[2]), "+f"(d[3])
        : "r"(a[0]), "r"(a[1]), "r"(a[2]), "r"(a[3]), "r"(b[0]), "r"(b[1]));
}
__device__ __forceinline__ void mma16816h(float* d, const u32* a, const u32* b) {
    asm volatile("mma.sync.aligned.m16n8k16.row.col.f32.f16.f16.f32 "
        "{%0,%1,%2,%3}, {%4,%5,%6,%7}, {%8,%9}, {%0,%1,%2,%3};"
        : "+f"(d[0]), "+f"(d[1]), "+f"(d[2]), "+f"(d[3])
        : "r"(a[0]), "r"(a[1]), "r"(a[2]), "r"(a[3]), "r"(b[0]), "r"(b[1]));
}
__device__ __forceinline__ u32 sw128(u32 b) {
    return b ^ ((b >> 3) & 0x70u);
}
__device__ __forceinline__ void split_store(float v, __nv_bfloat16* hi, __nv_bfloat16* lo, size_t i) {
    __nv_bfloat16 h = __float2bfloat16(v);
    hi[i] = h;
    lo[i] = __float2bfloat16(v - __bfloat162float(h));
}
__device__ __forceinline__ void split2(float a, float b, u32& hi, u32& lo) {
    __nv_bfloat16 ha = __float2bfloat16(a), hb = __float2bfloat16(b);
    hi = (u32)__bfloat16_as_ushort(ha) | ((u32)__bfloat16_as_ushort(hb) << 16);
    lo = (u32)__bfloat16_as_ushort(__float2bfloat16(a - __bfloat162float(ha)))
       | ((u32)__bfloat16_as_ushort(__float2bfloat16(b - __bfloat162float(hb))) << 16);
}

template<int W> __device__ __forceinline__ __nv_bfloat16* qsel() {
    if (W == 0) return g_qw;
    if (W == 1) return g_qwo;
    if (W == 2) return g_qwfc;
    return g_qwpr;
}
template<int W> __device__ __forceinline__ float* scsel() {
    if (W == 0) return g_sqkv;
    if (W == 1) return g_swo;
    if (W == 2) return g_swfc;
    if (W == 3) return g_swpr;
    return g_slm;
}
template<int A> __device__ __forceinline__ const __nv_bfloat16* ahisel() {
    if (A == 0) return g_hhi;
    if (A == 1) return g_atthi;
    return g_ffhi;
}
template<int A> __device__ __forceinline__ const __nv_bfloat16* alosel() {
    if (A == 0) return g_hlo;
    if (A == 1) return g_attlo;
    return g_fflo;
}

// ---------------- fake-quant (bf16 outputs, layer weights) ----------------
template<int WSEL, int NR>
__global__ void quant_kernel(const float* __restrict__ W, int rpl, int ld, int off)
{
    const int n = NR * 256;
    int blk = blockIdx.x;
    int l = blk / rpl, r = blk % rpl;
    int out_row = l * ld + off + r;
    const float* w = W + (size_t)blk * n;
    __nv_bfloat16* qb = qsel<WSEL>() + (size_t)out_row * n;
    int tid = threadIdx.x;

    float v[NR];
    float m1 = 0.f, m2 = 0.f;
    #pragma unroll
    for (int j = 0; j < NR; j++) {
        v[j] = w[tid + j * 256];
        float a = fabsf(v[j]);
        if (a > m1) { m2 = m1; m1 = a; }
        else if (a > m2) { m2 = a; }
    }
    __shared__ float s1[256], s2[256];
    s1[tid] = m1; s2[tid] = m2;
    __syncthreads();
    for (int o = 128; o; o >>= 1) {
        if (tid < o) {
            float a1 = s1[tid], a2 = s2[tid];
            float b1 = s1[tid + o], b2 = s2[tid + o];
            s1[tid] = fmaxf(a1, b1);
            s2[tid] = fmaxf(fminf(a1, b1), fmaxf(a2, b2));
        }
        __syncthreads();
    }
    __shared__ float sh_clip, sh_scale;
    if (tid == 0) {
        float M1 = s1[0], M2 = s2[0];
        float idxf = 0.9999984f * (float)(n - 1);
        float frac = idxf - (float)(n - 2);
        float clip = M2 * (1.0f - frac) + M1 * frac;
        float scale = fmaxf(__fdiv_rn(clip, 127.0f), 1.0f / 127.0f);
        sh_clip = clip;
        sh_scale = scale;
        scsel<WSEL>()[out_row] = __half2float(__float2half_rn(scale));
    }
    __syncthreads();
    float clip = sh_clip, scale = sh_scale;
    #pragma unroll
    for (int j = 0; j < NR; j++) {
        float c = fminf(fmaxf(v[j], -clip), clip);
        float q = rintf(__fdiv_rn(c, scale));
        q = fminf(fmaxf(q, -127.f), 127.f);
        qb[tid + j * 256] = __float2bfloat16(q);
    }
}

// ---------------- fake-quant (fp16 output, lm_head) ----------------
__global__ void quant_lmh_kernel(const float* __restrict__ W)
{
    const int n = D_;
    int out_row = blockIdx.x;
    const float* w = W + (size_t)out_row * n;
    __half* qb = g_qlmh + (size_t)out_row * n;
    int tid = threadIdx.x;

    float v[4];
    float m1 = 0.f, m2 = 0.f;
    #pragma unroll
    for (int j = 0; j < 4; j++) {
        v[j] = w[tid + j * 256];
        float a = fabsf(v[j]);
        if (a > m1) { m2 = m1; m1 = a; }
        else if (a > m2) { m2 = a; }
    }
    __shared__ float s1[256], s2[256];
    s1[tid] = m1; s2[tid] = m2;
    __syncthreads();
    for (int o = 128; o; o >>= 1) {
        if (tid < o) {
            float a1 = s1[tid], a2 = s2[tid];
            float b1 = s1[tid + o], b2 = s2[tid + o];
            s1[tid] = fmaxf(a1, b1);
            s2[tid] = fmaxf(fminf(a1, b1), fmaxf(a2, b2));
        }
        __syncthreads();
    }
    __shared__ float sh_clip, sh_scale;
    if (tid == 0) {
        float M1 = s1[0], M2 = s2[0];
        float idxf = 0.9999984f * (float)(n - 1);
        float frac = idxf - (float)(n - 2);
        float clip = M2 * (1.0f - frac) + M1 * frac;
        float scale = fmaxf(__fdiv_rn(clip, 127.0f), 1.0f / 127.0f);
        sh_clip = clip;
        sh_scale = scale;
        g_slm[out_row] = __half2float(__float2half_rn(scale));
    }
    __syncthreads();
    float clip = sh_clip, scale = sh_scale;
    #pragma unroll
    for (int j = 0; j < 4; j++) {
        float c = fminf(fmaxf(v[j], -clip), clip);
        float q = rintf(__fdiv_rn(c, scale));
        q = fminf(fmaxf(q, -127.f), 127.f);
        qb[tid + j * 256] = __float2half_rn(q);   // small integer: exact in fp16
    }
}

// ---------------- embedding ----------------
__global__ void embed_kernel(const int* __restrict__ idx, const float* __restrict__ emb)
{
    int i = blockIdx.x * blockDim.x + threadIdx.x;
    int s = i >> 10, d = i & 1023;
    g_x[i] = emb[(size_t)idx[s] * D_ + d];
}

// ---------------- rmsnorm -> bf16 hi/lo ----------------
__global__ void rmsnorm_split_kernel()
{
    int row = blockIdx.x;
    const float* xr = g_x + (size_t)row * D_;
    int tid = threadIdx.x;
    float ss = 0.f;
    for (int i = tid; i < D_; i += 256) { float v = xr[i]; ss += v * v; }
    __shared__ float sh[256];
    sh[tid] = ss; __syncthreads();
    for (int o = 128; o; o >>= 1) {
        if (tid < o) sh[tid] += sh[tid + o];
        __syncthreads();
    }
    float r = rsqrtf(sh[0] / (float)D_ + EPS_);
    for (int i = tid; i < D_; i += 256) {
        split_store(xr[i] * r, g_hhi, g_hlo, (size_t)row * D_ + i);
    }
}

// ---------------- final rmsnorm -> fp16 ----------------
__global__ void rmsnorm_h_kernel()
{
    int row = blockIdx.x;
    const float* xr = g_x + (size_t)row * D_;
    int tid = threadIdx.x;
    float ss = 0.f;
    for (int i = tid; i < D_; i += 256) { float v = xr[i]; ss += v * v; }
    __shared__ float sh[256];
    sh[tid] = ss; __syncthreads();
    for (int o = 128; o; o >>= 1) {
        if (tid < o) sh[tid] += sh[tid + o];
        __syncthreads();
    }
    float r = rsqrtf(sh[0] / (float)D_ + EPS_);
    for (int i = tid; i < D_; i += 256) {
        g_h16[(size_t)row * D_ + i] = __float2half_rn(xr[i] * r);
    }
}

// ---------------- merged per-head RMS + RoPE + gain ----------------
__global__ void qkpost_kernel(const float* __restrict__ gain)
{
    int warp = (blockIdx.x * blockDim.x + threadIdx.x) >> 5;
    int lane = threadIdx.x & 31;
    int s = warp / 20, j = warp % 20;
    if (s >= S_) return;
    int isq = (j < 16);
    int h = isq ? j : j - 16;
    int off = isq ? 0 : 1024;
    const float* base = g_qkv + (size_t)s * QKVD_ + off + h * HD_;
    float e0 = base[lane], e1 = base[lane + 32];
    float ss = e0 * e0 + e1 * e1;
    #pragma unroll
    for (int o = 16; o; o >>= 1) ss += __shfl_xor_sync(0xffffffffu, ss, o);
    float r = rsqrtf(ss * (1.f / 64.f) + EPS_);
    e0 *= r; e1 *= r;
    float inv = (float)exp(-((double)lane / 32.0) * 9.210340371976184);
    float f = (float)s * inv;
    float c  = (float)cos((double)f);
    float sn = (float)sin((double)f);
    float o0 =  e0 * c + e1 * sn;
    float o1 = -e0 * sn + e1 * c;
    if (isq) {
        float g = gain[h] * 0.125f;
        split_store(o0 * g, g_qhi, g_qlo, (size_t)s * D_ + h * HD_ + lane);
        split_store(o1 * g, g_qhi, g_qlo, (size_t)s * D_ + h * HD_ + lane + 32);
    } else {
        split_store(o0, g_khi, g_klo, (size_t)s * KVD_ + h * HD_ + lane);
        split_store(o1, g_khi, g_klo, (size_t)s * KVD_ + h * HD_ + lane + 32);
    }
}

// ---------------- V transpose ----------------
__global__ void vtrans_kernel()
{
    __shared__ float t[32][33];
    int s0 = blockIdx.x * 32, c0 = blockIdx.y * 32;
    int tx = threadIdx.x, ty = threadIdx.y;
    #pragma unroll
    for (int k = 0; k < 32; k += 8)
        t[ty + k][tx] = g_qkv[(size_t)(s0 + ty + k) * QKVD_ + 1280 + c0 + tx];
    __syncthreads();
    #pragma unroll
    for (int k = 0; k < 32; k += 8) {
        float v = t[tx][ty + k];
        split_store(v, g_vthi, g_vtlo, (size_t)(c0 + ty + k) * S_ + s0 + tx);
    }
}

// ---------------- fused flash attention: 128-row Q tiles, 256 threads ----------------
#define FA_DSM (32768 + 2 * 32768 + 1024)

__global__ __launch_bounds__(256, 1) void flash_kernel()
{
    int bi = 7 - (int)blockIdx.x;
    int h = blockIdx.y, kvh = h >> 2;
    extern __shared__ char fsm[];
    u32 base = (smem_u32(fsm) + 1023u) & ~1023u;

    int tid = threadIdx.x, lane = tid & 31, w = tid >> 5;
    int tig = lane & 3, grp = lane >> 2;

    for (int id = tid; id < 1024; id += 256) {
        int r = id >> 3, ck = id & 7;
        u32 so = sw128((u32)(r * 128 + ck * 16));
        size_t gq = (size_t)(bi * 128 + r) * D_ + h * HD_ + ck * 8;
        cpasync16(base + so, g_qhi + gq);
        cpasync16(base + 16384 + so, g_qlo + gq);
    }
    asm volatile("cp.async.commit_group;");

    #define FA_LOAD(st, jt) do { \
        u32 sb_ = base + 32768 + (u32)(st) * 32768; \
        for (int id_ = tid; id_ < 512; id_ += 256) { \
            int r_ = id_ >> 3, ck_ = id_ & 7; \
            u32 so_ = sw128((u32)(r_ * 128 + ck_ * 16)); \
            size_t gk_ = (size_t)((jt) * 64 + r_) * KVD_ + kvh * HD_ + ck_ * 8; \
            cpasync16(sb_ + so_,         g_khi + gk_); \
            cpasync16(sb_ + 8192 + so_,  g_klo + gk_); \
            size_t gv_ = (size_t)(kvh * 64 + r_) * S_ + (jt) * 64 + ck_ * 8; \
            cpasync16(sb_ + 16384 + so_, g_vthi + gv_); \
            cpasync16(sb_ + 24576 + so_, g_vtlo + gv_); \
        } \
        asm volatile("cp.async.commit_group;"); \
    } while (0)

    int n = 2 * bi + 2;
    FA_LOAD(0, 0);

    asm volatile("cp.async.wait_group 1;");
    __syncthreads();
    u32 qh[4][4], ql[4][4];
    #pragma unroll
    for (int kc = 0; kc < 4; kc++) {
        int lr = w * 16 + (lane & 15);
        int ch = kc * 2 + (lane >> 4);
        u32 so = sw128((u32)(lr * 128 + ch * 16));
        ldm_x4(qh[kc][0], qh[kc][1], qh[kc][2], qh[kc][3], base + so);
        ldm_x4(ql[kc][0], ql[kc][1], ql[kc][2], ql[kc][3], base + 16384 + so);
    }

    float o[8][4];
    #pragma unroll
    for (int nd = 0; nd < 8; nd++) { o[nd][0]=0.f; o[nd][1]=0.f; o[nd][2]=0.f; o[nd][3]=0.f; }
    float m0 = -1e30f, m1 = -1e30f, l0 = 0.f, l1 = 0.f;

    for (int jt = 0; jt < n; jt++) {
        if (jt + 1 < n) {
            FA_LOAD((jt + 1) & 1, jt + 1);
            asm volatile("cp.async.wait_group 1;");
        } else {
            asm volatile("cp.async.wait_group 0;");
        }
        __syncthreads();

        u32 kb = base + 32768 + (u32)(jt & 1) * 32768;

        float s[8][4];
        #pragma unroll
        for (int ni = 0; ni < 8; ni++) { s[ni][0]=0.f; s[ni][1]=0.f; s[ni][2]=0.f; s[ni][3]=0.f; }
        #pragma unroll
        for (int kc = 0; kc < 4; kc++) {
            u32 bh[8][2], bl[8][2];
            #pragma unroll
            for (int nj = 0; nj < 4; nj++) {
                int g = lane >> 3;
                int lr = nj * 16 + (((g >> 1) & 1) << 3) + (lane & 7);
                int ch = kc * 2 + (g & 1);
                u32 so = sw128((u32)(lr * 128 + ch * 16));
                u32 r0, r1, r2, r3;
                ldm_x4(r0, r1, r2, r3, kb + so);
                bh[nj * 2][0] = r0; bh[nj * 2][1] = r1;
                bh[nj * 2 + 1][0] = r2; bh[nj * 2 + 1][1] = r3;
                ldm_x4(r0, r1, r2, r3, kb + 8192 + so);
                bl[nj * 2][0] = r0; bl[nj * 2][1] = r1;
                bl[nj * 2 + 1][0] = r2; bl[nj * 2 + 1][1] = r3;
            }
            #pragma unroll
            for (int ni = 0; ni < 8; ni++) {
                mma16816(s[ni], qh[kc], bh[ni]);
                mma16816(s[ni], qh[kc], bl[ni]);
                mma16816(s[ni], ql[kc], bh[ni]);
            }
        }

        if (jt >= 2 * bi) {
            int ci0 = bi * 128 + w * 16 + grp, ci1 = ci0 + 8;
            #pragma unroll
            for (int ni = 0; ni < 8; ni++) {
                int cj = jt * 64 + ni * 8 + tig * 2;
                if (cj     > ci0) s[ni][0] = -1e30f;
                if (cj + 1 > ci0) s[ni][1] = -1e30f;
                if (cj     > ci1) s[ni][2] = -1e30f;
                if (cj + 1 > ci1) s[ni][3] = -1e30f;
            }
        }

        float tm0 = -1e30f, tm1 = -1e30f;
        #pragma unroll
        for (int ni = 0; ni < 8; ni++) {
            tm0 = fmaxf(tm0, fmaxf(s[ni][0], s[ni][1]));
            tm1 = fmaxf(tm1, fmaxf(s[ni][2], s[ni][3]));
        }
        tm0 = fmaxf(tm0, __shfl_xor_sync(0xffffffffu, tm0, 1));
        tm0 = fmaxf(tm0, __shfl_xor_sync(0xffffffffu, tm0, 2));
        tm1 = fmaxf(tm1, __shfl_xor_sync(0xffffffffu, tm1, 1));
        tm1 = fmaxf(tm1, __shfl_xor_sync(0xffffffffu, tm1, 2));
        float mn0 = fmaxf(m0, tm0), mn1 = fmaxf(m1, tm1);
        float a0 = expf(m0 - mn0), a1 = expf(m1 - mn1);
        m0 = mn0; m1 = mn1;

        float rs0 = 0.f, rs1 = 0.f;
        #pragma unroll
        for (int ni = 0; ni < 8; ni++) {
            s[ni][0] = expf(s[ni][0] - mn0);
            s[ni][1] = expf(s[ni][1] - mn0);
            s[ni][2] = expf(s[ni][2] - mn1);
            s[ni][3] = expf(s[ni][3] - mn1);
            rs0 += s[ni][0] + s[ni][1];
            rs1 += s[ni][2] + s[ni][3];
        }
        rs0 += __shfl_xor_sync(0xffffffffu, rs0, 1);
        rs0 += __shfl_xor_sync(0xffffffffu, rs0, 2);
        rs1 += __shfl_xor_sync(0xffffffffu, rs1, 1);
        rs1 += __shfl_xor_sync(0xffffffffu, rs1, 2);
        l0 = l0 * a0 + rs0;
        l1 = l1 * a1 + rs1;
        #pragma unroll
        for (int nd = 0; nd < 8; nd++) {
            o[nd][0] *= a0; o[nd][1] *= a0;
            o[nd][2] *= a1; o[nd][3] *= a1;
        }

        u32 vbh = kb + 16384, vbl = kb + 24576;
        #pragma unroll
        for (int kc = 0; kc < 4; kc++) {
            u32 pah[4], pal[4];
            split2(s[2 * kc][0],     s[2 * kc][1],     pah[0], pal[0]);
            split2(s[2 * kc][2],     s[2 * kc][3],     pah[1], pal[1]);
            split2(s[2 * kc + 1][0], s[2 * kc + 1][1], pah[2], pal[2]);
            split2(s[2 * kc + 1][2], s[2 * kc + 1][3], pah[3], pal[3]);
            u32 vh[8][2], vl[8][2];
            #pragma unroll
            for (int nj = 0; nj < 4; nj++) {
                int g = lane >> 3;
                int lr = nj * 16 + (((g >> 1) & 1) << 3) + (lane & 7);
                int ch = kc * 2 + (g & 1);
                u32 so = sw128((u32)(lr * 128 + ch * 16));
                u32 r0, r1, r2, r3;
                ldm_x4(r0, r1, r2, r3, vbh + so);
                vh[nj * 2][0] = r0; vh[nj * 2][1] = r1;
                vh[nj * 2 + 1][0] = r2; vh[nj * 2 + 1][1] = r3;
                ldm_x4(r0, r1, r2, r3, vbl + so);
                vl[nj * 2][0] = r0; vl[nj * 2][1] = r1;
                vl[nj * 2 + 1][0] = r2; vl[nj * 2 + 1][1] = r3;
            }
            #pragma unroll
            for (int nd = 0; nd < 8; nd++) {
                mma16816(o[nd], pah, vh[nd]);
                mma16816(o[nd], pah, vl[nd]);
                mma16816(o[nd], pal, vh[nd]);
            }
        }
        __syncthreads();
    }

    float inv0 = 1.0f / l0, inv1 = 1.0f / l1;
    int gi0 = bi * 128 + w * 16 + grp;
    #pragma unroll
    for (int nd = 0; nd < 8; nd++) {
        int gd = h * HD_ + nd * 8 + tig * 2;
        split_store(o[nd][0] * inv0, g_atthi, g_attlo, (size_t)gi0 * D_ + gd);
        split_store(o[nd][1] * inv0, g_atthi, g_attlo, (size_t)gi0 * D_ + gd + 1);
        split_store(o[nd][2] * inv1, g_atthi, g_attlo, (size_t)(gi0 + 8) * D_ + gd);
        split_store(o[nd][3] * inv1, g_atthi, g_attlo, (size_t)(gi0 + 8) * D_ + gd + 1);
    }
    #undef FA_LOAD
}

// ---------------- shared GEMM pieces ----------------
template<int BM, int BN>
__device__ __forceinline__ void load_stage64(
    const __nv_bfloat16* Ahi, const __nv_bfloat16* Alo, const __nv_bfloat16* Bq,
    u32 sbase, int row0, int col0, int K, int k0, int tid)
{
    constexpr u32 ABYTES = (u32)BM * 128;
    for (int id = tid; id < BM * 8; id += 256) {
        int r = id >> 3, ck = id & 7;
        u32 so = sw128((u32)(r * 128 + ck * 16));
        size_t g = (size_t)(row0 + r) * K + k0 + ck * 8;
        cpasync16(sbase + so, Ahi + g);
        cpasync16(sbase + ABYTES + so, Alo + g);
    }
    for (int id = tid; id < BN * 8; id += 256) {
        int r = id >> 3, ck = id & 7;
        u32 so = sw128((u32)(r * 128 + ck * 16));
        cpasync16(sbase + 2 * ABYTES + so, Bq + (size_t)(col0 + r) * K + k0 + ck * 8);
    }
    asm volatile("cp.async.commit_group;");
}

template<int EPI>
__device__ __forceinline__ void epi_store(float v, int gr, int c, float* Cout, int ldc)
{
    if (EPI == 0) {
        g_qkv[(size_t)gr * QKVD_ + c] = v;
    } else if (EPI == 1) {
        g_x[(size_t)gr * D_ + c] += v;
    } else if (EPI == 2) {
        float t = fmaxf(v, 0.f);
        split_store(t * t, g_ffhi, g_fflo, (size_t)gr * FF_ + c);
    } else {
        Cout[(size_t)gr * ldc + c] = v;
    }
}

// ---------------- small GEMM: 128x64, 2-stage, 2 CTAs/SM ----------------
template<int EPI, int WSEL, int ASEL>
__global__ __launch_bounds__(256, 2)
void qgemm2_kernel(float* __restrict__ Cout, int layer, int N, int K, int ldc)
{
    constexpr int BM = 128, BN = 64;
    constexpr int MI = 2, NI = 4;
    constexpr u32 STB = (u32)(2 * BM + BN) * 128;

    extern __shared__ char dsm[];
    u32 base = (smem_u32(dsm) + 1023u) & ~1023u;

    int tid = threadIdx.x, lane = tid & 31, wid = tid >> 5;
    int wm = wid % 4, wn = wid / 4;
    int row0 = blockIdx.y * BM, col0 = blockIdx.x * BN;

    const __nv_bfloat16* Ahi = ahisel<ASEL>();
    const __nv_bfloat16* Alo = alosel<ASEL>();
    const __nv_bfloat16* Bq  = qsel<WSEL>() + (size_t)layer * N * K;
    const float* Sc = scsel<WSEL>() + (size_t)layer * N;

    float acc[MI][NI][4];
    #pragma unroll
    for (int mi = 0; mi < MI; mi++)
        #pragma unroll
        for (int ni = 0; ni < NI; ni++) {
            acc[mi][ni][0] = 0.f; acc[mi][ni][1] = 0.f;
            acc[mi][ni][2] = 0.f; acc[mi][ni][3] = 0.f;
        }

    int n = K >> 6;
    load_stage64<BM, BN>(Ahi, Alo, Bq, base,       row0, col0, K, 0,  tid);
    load_stage64<BM, BN>(Ahi, Alo, Bq, base + STB, row0, col0, K, 64, tid);

    for (int it = 0; it < n; it++) {
        if (it + 1 < n) { asm volatile("cp.async.wait_group 1;"); }
        else            { asm volatile("cp.async.wait_group 0;"); }
        __syncthreads();

        u32 sb = base + (u32)(it & 1) * STB;
        #pragma unroll
        for (int kc = 0; kc < 4; kc++) {
            u32 ah[MI][4], al[MI][4];
            #pragma unroll
            for (int mi = 0; mi < MI; mi++) {
                int lr = wm * 32 + mi * 16 + (lane & 15);
                int ch = kc * 2 + (lane >> 4);
                u32 so = sw128((u32)(lr * 128 + ch * 16));
                ldm_x4(ah[mi][0], ah[mi][1], ah[mi][2], ah[mi][3], sb + so);
                ldm_x4(al[mi][0], al[mi][1], al[mi][2], al[mi][3], sb + (u32)BM * 128 + so);
            }
            u32 bb[NI][2];
            #pragma unroll
            for (int nj = 0; nj < NI / 2; nj++) {
                int g = lane >> 3;
                int lr = wn * 32 + nj * 16 + (((g >> 1) & 1) << 3) + (lane & 7);
                int ch = kc * 2 + (g & 1);
                u32 r0, r1, r2, r3;
                ldm_x4(r0, r1, r2, r3, sb + 2u * BM * 128 + sw128((u32)(lr * 128 + ch * 16)));
                bb[nj * 2][0] = r0; bb[nj * 2][1] = r1;
                bb[nj * 2 + 1][0] = r2; bb[nj * 2 + 1][1] = r3;
            }
            #pragma unroll
            for (int mi = 0; mi < MI; mi++)
                #pragma unroll
                for (int ni = 0; ni < NI; ni++) {
                    mma16816(acc[mi][ni], ah[mi], bb[ni]);
                    mma16816(acc[mi][ni], al[mi], bb[ni]);
                }
        }
        __syncthreads();
        if (it + 2 < n)
            load_stage64<BM, BN>(Ahi, Alo, Bq, base + (u32)(it & 1) * STB,
                                 row0, col0, K, (it + 2) << 6, tid);
    }

    #pragma unroll
    for (int mi = 0; mi < MI; mi++) {
        #pragma unroll
        for (int ni = 0; ni < NI; ni++) {
            int gr0 = row0 + wm * 32 + mi * 16 + (lane >> 2);
            int gc  = col0 + wn * 32 + ni * 8 + ((lane & 3) << 1);
            #pragma unroll
            for (int half = 0; half < 2; half++) {
                int gr = gr0 + half * 8;
                #pragma unroll
                for (int e = 0; e < 2; e++) {
                    int c = gc + e;
                    if (c >= N) continue;
                    epi_store<EPI>(acc[mi][ni][half * 2 + e] * Sc[c], gr, c, Cout, ldc);
                }
            }
        }
    }
}

// ---------------- big GEMM: 128x128, 3-stage (bf16 hi/lo) ----------------
template<int EPI, int WSEL, int ASEL>
__global__ __launch_bounds__(256, 1)
void qgemm3_kernel(float* __restrict__ Cout, int layer, int N, int K, int ldc)
{
    constexpr int BM = 128, BN = 128;
    constexpr int MI = 4, NI = 4;
    constexpr u32 STB = (u32)(2 * BM + BN) * 128;

    extern __shared__ char dsm[];
    u32 base = (smem_u32(dsm) + 1023u) & ~1023u;

    int tid = threadIdx.x, lane = tid & 31, wid = tid >> 5;
    int wm = wid % 2, wn = wid / 2;
    int row0 = blockIdx.y * BM, col0 = blockIdx.x * BN;

    const __nv_bfloat16* Ahi = ahisel<ASEL>();
    const __nv_bfloat16* Alo = alosel<ASEL>();
    const __nv_bfloat16* Bq  = qsel<WSEL>() + (size_t)layer * N * K;
    const float* Sc = scsel<WSEL>() + (size_t)layer * N;

    float acc[MI][NI][4];
    #pragma unroll
    for (int mi = 0; mi < MI; mi++)
        #pragma unroll
        for (int ni = 0; ni < NI; ni++) {
            acc[mi][ni][0] = 0.f; acc[mi][ni][1] = 0.f;
            acc[mi][ni][2] = 0.f; acc[mi][ni][3] = 0.f;
        }

    int n = K >> 6;
    load_stage64<BM, BN>(Ahi, Alo, Bq, base,       row0, col0, K, 0,  tid);
    load_stage64<BM, BN>(Ahi, Alo, Bq, base + STB, row0, col0, K, 64, tid);

    for (int it = 0; it < n; it++) {
        asm volatile("cp.async.wait_group 1;");
        __syncthreads();

        int ldst = it + 2;
        if (ldst < n) {
            load_stage64<BM, BN>(Ahi, Alo, Bq, base + (u32)(ldst % 3) * STB,
                                 row0, col0, K, ldst << 6, tid);
        } else {
            asm volatile("cp.async.commit_group;");
        }

        u32 sb = base + (u32)(it % 3) * STB;
        #pragma unroll
        for (int kc = 0; kc < 4; kc++) {
            u32 ah[MI][4], al[MI][4];
            #pragma unroll
            for (int mi = 0; mi < MI; mi++) {
                int lr = wm * 64 + mi * 16 + (lane & 15);
                int ch = kc * 2 + (lane >> 4);
                u32 so = sw128((u32)(lr * 128 + ch * 16));
                ldm_x4(ah[mi][0], ah[mi][1], ah[mi][2], ah[mi][3], sb + so);
                ldm_x4(al[mi][0], al[mi][1], al[mi][2], al[mi][3], sb + (u32)BM * 128 + so);
            }
            u32 bb[NI][2];
            #pragma unroll
            for (int nj = 0; nj < NI / 2; nj++) {
                int g = lane >> 3;
                int lr = wn * 32 + nj * 16 + (((g >> 1) & 1) << 3) + (lane & 7);
                int ch = kc * 2 + (g & 1);
                u32 r0, r1, r2, r3;
                ldm_x4(r0, r1, r2, r3, sb + 2u * BM * 128 + sw128((u32)(lr * 128 + ch * 16)));
                bb[nj * 2][0] = r0; bb[nj * 2][1] = r1;
                bb[nj * 2 + 1][0] = r2; bb[nj * 2 + 1][1] = r3;
            }
            #pragma unroll
            for (int mi = 0; mi < MI; mi++)
                #pragma unroll
                for (int ni = 0; ni < NI; ni++) {
                    mma16816(acc[mi][ni], ah[mi], bb[ni]);
                    mma16816(acc[mi][ni], al[mi], bb[ni]);
                }
        }
    }

    #pragma unroll
    for (int mi = 0; mi < MI; mi++) {
        #pragma unroll
        for (int ni = 0; ni < NI; ni++) {
            int gr0 = row0 + wm * 64 + mi * 16 + (lane >> 2);
            int gc  = col0 + wn * 32 + ni * 8 + ((lane & 3) << 1);
            #pragma unroll
            for (int half = 0; half < 2; half++) {
                int gr = gr0 + half * 8;
                #pragma unroll
                for (int e = 0; e < 2; e++) {
                    int c = gc + e;
                    if (c >= N) continue;
                    epi_store<EPI>(acc[mi][ni][half * 2 + e] * Sc[c], gr, c, Cout, ldc);
                }
            }
        }
    }
}

// ---------------- lm_head GEMM: 128x128, 3-stage, fp16 single-plane ----------------
__global__ __launch_bounds__(256, 1)
void qgemmh_kernel(float* __restrict__ Cout, int N, int K, int ldc)
{
    constexpr int BM = 128, BN = 128;
    constexpr int MI = 4, NI = 4;
    constexpr u32 STB = (u32)(BM + BN) * 128;   // 32768

    extern __shared__ char dsm[];
    u32 base = (smem_u32(dsm) + 1023u) & ~1023u;

    int tid = threadIdx.x, lane = tid & 31, wid = tid >> 5;
    int wm = wid % 2, wn = wid / 2;
    int row0 = blockIdx.y * BM, col0 = blockIdx.x * BN;

    const __half* A = g_h16;
    const __half* Bq = g_qlmh;
    const float* Sc = g_slm;

    float acc[MI][NI][4];
    #pragma unroll
    for (int mi = 0; mi < MI; mi++)
        #pragma unroll
        for (int ni = 0; ni < NI; ni++) {
            acc[mi][ni][0] = 0.f; acc[mi][ni][1] = 0.f;
            acc[mi][ni][2] = 0.f; acc[mi][ni][3] = 0.f;
        }

    #define LMLOAD(sbase, k0) do { \
        for (int id = tid; id < BM * 8; id += 256) { \
            int r = id >> 3, ck = id & 7; \
            u32 so = sw128((u32)(r * 128 + ck * 16)); \
            cpasync16((sbase) + so, A + (size_t)(row0 + r) * K + (k0) + ck * 8); \
        } \
        for (int id = tid; id < BN * 8; id += 256) { \
            int r = id >> 3, ck = id & 7; \
            u32 so = sw128((u32)(r * 128 + ck * 16)); \
            cpasync16((sbase) + (u32)BM * 128 + so, Bq + (size_t)(col0 + r) * K + (k0) + ck * 8); \
        } \
        asm volatile("cp.async.commit_group;"); \
    } while (0)

    int n = K >> 6;
    LMLOAD(base, 0);
    LMLOAD(base + STB, 64);

    for (int it = 0; it < n; it++) {
        asm volatile("cp.async.wait_group 1;");
        __syncthreads();

        int ldst = it + 2;
        if (ldst < n) {
            LMLOAD(base + (u32)(ldst % 3) * STB, ldst << 6);
        } else {
            asm volatile("cp.async.commit_group;");
        }

        u32 sb = base + (u32)(it % 3) * STB;
        #pragma unroll
        for (int kc = 0; kc < 4; kc++) {
            u32 ah[MI][4];
            #pragma unroll
            for (int mi = 0; mi < MI; mi++) {
                int lr = wm * 64 + mi * 16 + (lane & 15);
                int ch = kc * 2 + (lane >> 4);
                u32 so = sw128((u32)(lr * 128 + ch * 16));
                ldm_x4(ah[mi][0], ah[mi][1], ah[mi][2], ah[mi][3], sb + so);
            }
            u32 bb[NI][2];
            #pragma unroll
            for (int nj = 0; nj < NI / 2; nj++) {
                int g = lane >> 3;
                int lr = wn * 32 + nj * 16 + (((g >> 1) & 1) << 3) + (lane & 7);
                int ch = kc * 2 + (g & 1);
                u32 r0, r1, r2, r3;
                ldm_x4(r0, r1, r2, r3, sb + (u32)BM * 128 + sw128((u32)(lr * 128 + ch * 16)));
                bb[nj * 2][0] = r0; bb[nj * 2][1] = r1;
                bb[nj * 2 + 1][0] = r2; bb[nj * 2 + 1][1] = r3;
            }
            #pragma unroll
            for (int mi = 0; mi < MI; mi++)
                #pragma unroll
                for (int ni = 0; ni < NI; ni++)
                    mma16816h(acc[mi][ni], ah[mi], bb[ni]);
        }
    }
    #undef LMLOAD

    #pragma unroll
    for (int mi = 0; mi < MI; mi++) {
        #pragma unroll
        for (int ni = 0; ni < NI; ni++) {
            int gr0 = row0 + wm * 64 + mi * 16 + (lane >> 2);
            int gc  = col0 + wn * 32 + ni * 8 + ((lane & 3) << 1);
            #pragma unroll
            for (int half = 0; half < 2; half++) {
                int gr = gr0 + half * 8;
                #pragma unroll
                for (int e = 0; e < 2; e++) {
                    int c = gc + e;
                    if (c >= N) continue;
                    Cout[(size_t)gr * ldc + c] = acc[mi][ni][half * 2 + e] * Sc[c];
                }
            }
        }
    }
}

#define DSM_SMALL (2 * (2 * 128 + 64)  * 128 + 1024)
#define DSM_BIG   (3 * (2 * 128 + 128) * 128 + 1024)
#define DSM_LM    (3 * (128 + 128) * 128 + 1024)

// ---------------- host orchestration ----------------
extern "C" void kernel_launch(void* const* d_in, const int* in_sizes, int n_in,
                              void* d_out, int out_size)
{
    (void)in_sizes; (void)n_in; (void)out_size;
    const int*   idx = (const int*)  d_in[0];
    const float* emb = (const float*)d_in[1];
    const float* wq  = (const float*)d_in[2];
    const float* wk  = (const float*)d_in[3];
    const float* wv  = (const float*)d_in[4];
    const float* wo  = (const float*)d_in[5];
    const float* qg  = (const float*)d_in[6];
    const float* wfc = (const float*)d_in[7];
    const float* wpr = (const float*)d_in[8];
    const float* lm  = (const float*)d_in[9];
    float* out = (float*)d_out;

    cudaFuncSetAttribute(qgemm2_kernel<0, 0, 0>,
                         cudaFuncAttributeMaxDynamicSharedMemorySize, DSM_SMALL);
    cudaFuncSetAttribute(qgemm2_kernel<1, 1, 1>,
                         cudaFuncAttributeMaxDynamicSharedMemorySize, DSM_SMALL);
    cudaFuncSetAttribute(qgemm2_kernel<1, 3, 2>,
                         cudaFuncAttributeMaxDynamicSharedMemorySize, DSM_SMALL);
    cudaFuncSetAttribute(qgemm3_kernel<2, 2, 0>,
                         cudaFuncAttributeMaxDynamicSharedMemorySize, DSM_BIG);
    cudaFuncSetAttribute(qgemmh_kernel,
                         cudaFuncAttributeMaxDynamicSharedMemorySize, DSM_LM);
    cudaFuncSetAttribute(flash_kernel,
                         cudaFuncAttributeMaxDynamicSharedMemorySize, FA_DSM);

    quant_kernel<0, 4><<<L_ * D_,    256>>>(wq,  D_,   QKVD_, 0);
    quant_kernel<0, 4><<<L_ * KVD_,  256>>>(wk,  KVD_, QKVD_, 1024);
    quant_kernel<0, 4><<<L_ * KVD_,  256>>>(wv,  KVD_, QKVD_, 1280);
    quant_kernel<1, 4><<<L_ * D_,    256>>>(wo,  L_ * D_,  0, 0);
    quant_kernel<2, 4><<<L_ * FF_,   256>>>(wfc, L_ * FF_, 0, 0);
    quant_kernel<3, 16><<<L_ * D_,   256>>>(wpr, L_ * D_,  0, 0);
    quant_lmh_kernel<<<V_,           256>>>(lm);

    embed_kernel<<<(S_ * D_) / 256, 256>>>(idx, emb);

    for (int l = 0; l < L_; l++) {
        rmsnorm_split_kernel<<<S_, 256>>>();

        qgemm2_kernel<0, 0, 0><<<dim3(QKVD_ / 64, S_ / 128), 256, DSM_SMALL>>>(
            nullptr, l, QKVD_, D_, QKVD_);

        qkpost_kernel<<<(S_ * 20) / 4, 128>>>(qg + l * H_);
        vtrans_kernel<<<dim3(S_ / 32, KVD_ / 32), dim3(32, 8)>>>();

        flash_kernel<<<dim3(8, H_), 256, FA_DSM>>>();

        qgemm2_kernel<1, 1, 1><<<dim3(D_ / 64, S_ / 128), 256, DSM_SMALL>>>(
            nullptr, l, D_, D_, D_);

        rmsnorm_split_kernel<<<S_, 256>>>();

        qgemm3_kernel<2, 2, 0><<<dim3(FF_ / 128, S_ / 128), 256, DSM_BIG>>>(
            nullptr, l, FF_, D_, FF_);

        qgemm2_kernel<1, 3, 2><<<dim3(D_ / 64, S_ / 128), 256, DSM_SMALL>>>(
            nullptr, l, D_, FF_, D_);
    }

    // final norm (fp16) + fp16 lm_head
    rmsnorm_h_kernel<<<S_, 256>>>();
    qgemmh_kernel<<<dim3(VPAD_ / 128, S_ / 128), 256, DSM_LM>>>(
        out, V_, D_, V_);
}